// round 3
// baseline (speedup 1.0000x reference)
#include <cuda_runtime.h>
#include <math.h>

#define NN    50000
#define EE    200000
#define ET    250000   // EE + NN self loops
#define GG    2000
#define DMF   512
#define NHEAD 4
#define HIDD  128
#define NEG_SLOPE 0.2f
#define BN_EPS 1e-5f

// ---------------- scratch (device globals; no allocation allowed) ----------
__device__ float d_h   [NN * DMF];     // h = x @ W  (per layer)
__device__ float d_xb  [NN * DMF];     // layer output / next layer input
__device__ float d_agg [NN * DMF];     // segment-sum accumulator (init = bias)
__device__ float d_ssrc[NN * NHEAD];
__device__ float d_sdst[NN * NHEAD];
__device__ float d_m   [NN * NHEAD];   // segment max
__device__ float d_den [NN * NHEAD];   // segment sum of exp
__device__ float d_ex  [ET * NHEAD];   // per-edge logits, then exp
__device__ float d_bnsum[DMF];
__device__ float d_bnss [DMF];
__device__ float d_scale[DMF];
__device__ float d_shift[DMF];
__device__ float d_gsum [GG * DMF];
__device__ int   d_gmaxi[GG * DMF];
__device__ float d_gcnt [GG];
__device__ float d_h1   [GG * 128];
__device__ float d_h2   [GG * 64];

// ---------------- helpers ----------------
__device__ __forceinline__ void redAddV4(float* p, float4 v) {
    asm volatile("red.global.add.v4.f32 [%0], {%1,%2,%3,%4};"
                 :: "l"(p), "f"(v.x), "f"(v.y), "f"(v.z), "f"(v.w) : "memory");
}

__device__ __forceinline__ void atomicMaxF(float* a, float v) {
    // works for mixed-sign floats with init = very negative float
    if (v >= 0.0f) atomicMax((int*)a, __float_as_int(v));
    else           atomicMin((unsigned int*)a, (unsigned int)__float_as_int(v));
}

// ---------------- GEMM: C[M,512] = A[M,K] @ B[K,512] ----------------------
// 128x128 tile, BK=8, 256 threads, 8x8 micro-tile.
__global__ void __launch_bounds__(256)
gemm_kernel(const float* __restrict__ A, const float* __restrict__ B,
            float* __restrict__ C, int M, int K) {
    __shared__ float As[8][128];
    __shared__ float Bs[8][128];

    const int bx = blockIdx.x;   // N tile (0..3)
    const int by = blockIdx.y;   // M tile
    const int tid = threadIdx.x;
    const int tx = tid & 15, ty = tid >> 4;

    const int aRow = tid >> 1;          // 0..127
    const int aCol = (tid & 1) * 4;     // 0 or 4
    const int bRow = tid >> 5;          // 0..7
    const int bCol = (tid & 31) * 4;

    const float* Ab = A + (long long)(by * 128) * K;
    const float* Bb = B + bx * 128;

    float acc[8][8];
#pragma unroll
    for (int i = 0; i < 8; i++)
#pragma unroll
        for (int j = 0; j < 8; j++) acc[i][j] = 0.0f;

    const int gRow = by * 128 + aRow;

    for (int k0 = 0; k0 < K; k0 += 8) {
        float4 av = make_float4(0.f, 0.f, 0.f, 0.f);
        if (gRow < M) av = *(const float4*)(Ab + (long long)aRow * K + k0 + aCol);
        As[aCol + 0][aRow] = av.x;
        As[aCol + 1][aRow] = av.y;
        As[aCol + 2][aRow] = av.z;
        As[aCol + 3][aRow] = av.w;

        float4 bv = *(const float4*)(Bb + (long long)(k0 + bRow) * DMF + bCol);
        *(float4*)&Bs[bRow][bCol] = bv;
        __syncthreads();

#pragma unroll
        for (int k = 0; k < 8; k++) {
            float rm[8], rn[8];
#pragma unroll
            for (int i = 0; i < 8; i++) rm[i] = As[k][ty * 8 + i];
#pragma unroll
            for (int j = 0; j < 8; j++) rn[j] = Bs[k][tx * 8 + j];
#pragma unroll
            for (int i = 0; i < 8; i++)
#pragma unroll
                for (int j = 0; j < 8; j++) acc[i][j] = fmaf(rm[i], rn[j], acc[i][j]);
        }
        __syncthreads();
    }

#pragma unroll
    for (int i = 0; i < 8; i++) {
        int row = by * 128 + ty * 8 + i;
        if (row < M) {
#pragma unroll
            for (int j = 0; j < 8; j += 4) {
                float4 v = make_float4(acc[i][j], acc[i][j+1], acc[i][j+2], acc[i][j+3]);
                *(float4*)(C + (long long)row * DMF + bx * 128 + tx * 8 + j) = v;
            }
        }
    }
}

// ---------------- attention scores + segment init ----------------
__global__ void scores_kernel(const float* __restrict__ h,
                              const float* __restrict__ as_,
                              const float* __restrict__ ad_) {
    int n = blockIdx.x;
    int warp = threadIdx.x >> 5, lane = threadIdx.x & 31;
    const float* hp  = h   + (long long)n * DMF + warp * HIDD;
    const float* asp = as_ + warp * HIDD;
    const float* adp = ad_ + warp * HIDD;
    float s1 = 0.f, s2 = 0.f;
#pragma unroll
    for (int i = 0; i < 4; i++) {
        float v = hp[lane + 32 * i];
        s1 += v * asp[lane + 32 * i];
        s2 += v * adp[lane + 32 * i];
    }
#pragma unroll
    for (int o = 16; o; o >>= 1) {
        s1 += __shfl_down_sync(0xffffffffu, s1, o);
        s2 += __shfl_down_sync(0xffffffffu, s2, o);
    }
    if (lane == 0) {
        d_ssrc[n * NHEAD + warp] = s1;
        d_sdst[n * NHEAD + warp] = s2;
        d_m  [n * NHEAD + warp] = -1e30f;
        d_den[n * NHEAD + warp] = 0.f;
    }
}

// ---------------- edge pass 1: logits + segment max ----------------
__global__ void edge_max_kernel(const int* __restrict__ ei) {
    int idx = blockIdx.x * blockDim.x + threadIdx.x;
    if (idx >= ET * NHEAD) return;
    int e = idx >> 2, h = idx & 3;
    int s, d;
    if (e < EE) { s = ei[e]; d = ei[EE + e]; } else { s = d = e - EE; }
    float v = d_ssrc[s * NHEAD + h] + d_sdst[d * NHEAD + h];
    v = (v > 0.f) ? v : NEG_SLOPE * v;
    d_ex[idx] = v;
    atomicMaxF(&d_m[d * NHEAD + h], v);
}

// ---------------- edge pass 2: exp + segment sum ----------------
__global__ void edge_exp_kernel(const int* __restrict__ ei) {
    int idx = blockIdx.x * blockDim.x + threadIdx.x;
    if (idx >= ET * NHEAD) return;
    int e = idx >> 2, h = idx & 3;
    int d;
    if (e < EE) d = ei[EE + e]; else d = e - EE;
    float ex = expf(d_ex[idx] - d_m[d * NHEAD + h]);
    d_ex[idx] = ex;
    atomicAdd(&d_den[d * NHEAD + h], ex);
}

// ---------------- init accumulator with bias ----------------
__global__ void init_agg_kernel(const float* __restrict__ bias) {
    int i = blockIdx.x * blockDim.x + threadIdx.x;
    if (i < NN * DMF) d_agg[i] = bias[i & (DMF - 1)];
}

// ---------------- weighted scatter aggregation ----------------
__global__ void aggregate_kernel(const int* __restrict__ ei) {
    int i = blockIdx.x * blockDim.x + threadIdx.x;
    if (i >= ET * 128) return;              // 128 float4 lanes per edge
    int e = i >> 7, j = i & 127;
    int head = j >> 5;
    int s, d;
    if (e < EE) { s = ei[e]; d = ei[EE + e]; } else { s = d = e - EE; }
    float alpha = d_ex[e * NHEAD + head] / d_den[d * NHEAD + head];
    float4 hv = *(const float4*)(d_h + (long long)s * DMF + j * 4);
    hv.x *= alpha; hv.y *= alpha; hv.z *= alpha; hv.w *= alpha;
    redAddV4(d_agg + (long long)d * DMF + j * 4, hv);
}

// ---------------- batch norm ----------------
__global__ void bn_zero_kernel() {
    int c = threadIdx.x;
    d_bnsum[c] = 0.f; d_bnss[c] = 0.f;
}

__global__ void __launch_bounds__(512)
bn_stats_kernel() {
    int c = threadIdx.x;
    int r0 = blockIdx.x * 64;
    int rend = min(r0 + 64, NN);
    float s = 0.f, ss = 0.f;
    for (int r = r0; r < rend; r++) {
        float v = d_agg[(long long)r * DMF + c];
        s += v; ss += v * v;
    }
    atomicAdd(&d_bnsum[c], s);
    atomicAdd(&d_bnss[c], ss);
}

__global__ void bn_finalize_kernel(const float* __restrict__ g,
                                   const float* __restrict__ be) {
    int c = threadIdx.x;
    float mean = d_bnsum[c] * (1.0f / NN);
    float var  = d_bnss[c] * (1.0f / NN) - mean * mean;
    float sc = g[c] * rsqrtf(var + BN_EPS);
    d_scale[c] = sc;
    d_shift[c] = be[c] - mean * sc;
}

__global__ void bn_apply_kernel() {
    int i = blockIdx.x * blockDim.x + threadIdx.x;
    if (i >= NN * DMF) return;
    int c = i & (DMF - 1);
    float v = d_agg[i] * d_scale[c] + d_shift[c];
    d_xb[i] = fmaxf(v, 0.f);
}

// ---------------- pooling ----------------
__global__ void pool_init_kernel() {
    int i = blockIdx.x * blockDim.x + threadIdx.x;
    if (i < GG * DMF) { d_gsum[i] = 0.f; d_gmaxi[i] = 0; }
    if (i < GG) d_gcnt[i] = 0.f;
}

__global__ void pool_cnt_kernel(const int* __restrict__ batch) {
    int n = blockIdx.x * blockDim.x + threadIdx.x;
    if (n < NN) atomicAdd(&d_gcnt[batch[n]], 1.0f);
}

__global__ void pool_feat_kernel(const int* __restrict__ batch) {
    int i = blockIdx.x * blockDim.x + threadIdx.x;
    if (i >= NN * 128) return;              // float4 lanes
    int n = i >> 7, c4 = i & 127;
    int g = batch[n];
    float4 v = *(const float4*)(d_xb + (long long)n * DMF + c4 * 4);
    redAddV4(d_gsum + (long long)g * DMF + c4 * 4, v);
    int* mp = d_gmaxi + (long long)g * DMF + c4 * 4;
    atomicMax(mp + 0, __float_as_int(v.x));   // values >= 0 after ReLU
    atomicMax(mp + 1, __float_as_int(v.y));
    atomicMax(mp + 2, __float_as_int(v.z));
    atomicMax(mp + 3, __float_as_int(v.w));
}

// ---------------- graph-level MLP ----------------
__global__ void __launch_bounds__(128)
mlp1_kernel(const float* __restrict__ c1w, const float* __restrict__ c1b) {
    __shared__ float hrow[1024];
    int g = blockIdx.x, t = threadIdx.x;
    float cnt = fmaxf(d_gcnt[g], 1.0f);
    float inv = 1.0f / cnt;
    for (int c = t; c < DMF; c += 128) {
        hrow[c]       = d_gsum[g * DMF + c] * inv;
        hrow[DMF + c] = __int_as_float(d_gmaxi[g * DMF + c]);
    }
    __syncthreads();
    float acc = c1b[t];
    for (int k = 0; k < 1024; k++) acc = fmaf(hrow[k], c1w[k * 128 + t], acc);
    d_h1[g * 128 + t] = fmaxf(acc, 0.f);
}

__global__ void __launch_bounds__(64)
mlp2_kernel(const float* __restrict__ c2w, const float* __restrict__ c2b) {
    __shared__ float hrow[128];
    int g = blockIdx.x, t = threadIdx.x;
    for (int c = t; c < 128; c += 64) hrow[c] = d_h1[g * 128 + c];
    __syncthreads();
    float acc = c2b[t];
    for (int k = 0; k < 128; k++) acc = fmaf(hrow[k], c2w[k * 64 + t], acc);
    d_h2[g * 64 + t] = fmaxf(acc, 0.f);
}

__global__ void mlp3_kernel(const float* __restrict__ c3w,
                            const float* __restrict__ c3b,
                            float* __restrict__ out) {
    int g = blockIdx.x * blockDim.x + threadIdx.x;
    if (g >= GG) return;
    float acc = c3b[0];
    for (int k = 0; k < 64; k++) acc = fmaf(d_h2[g * 64 + k], c3w[k], acc);
    out[g] = 1.0f / (1.0f + expf(-acc));
}

// ---------------- launch ----------------
extern "C" void kernel_launch(void* const* d_in, const int* in_sizes, int n_in,
                              void* d_out, int out_size) {
    const float* x     = (const float*)d_in[0];
    const int*   ei    = (const int*)  d_in[1];
    const int*   batch = (const int*)  d_in[2];

    const float* W [3] = {(const float*)d_in[3],  (const float*)d_in[9],  (const float*)d_in[15]};
    const float* AS[3] = {(const float*)d_in[4],  (const float*)d_in[10], (const float*)d_in[16]};
    const float* AD[3] = {(const float*)d_in[5],  (const float*)d_in[11], (const float*)d_in[17]};
    const float* BB[3] = {(const float*)d_in[6],  (const float*)d_in[12], (const float*)d_in[18]};
    const float* GM[3] = {(const float*)d_in[7],  (const float*)d_in[13], (const float*)d_in[19]};
    const float* BE[3] = {(const float*)d_in[8],  (const float*)d_in[14], (const float*)d_in[20]};

    const float* c1w = (const float*)d_in[21];
    const float* c1b = (const float*)d_in[22];
    const float* c2w = (const float*)d_in[23];
    const float* c2b = (const float*)d_in[24];
    const float* c3w = (const float*)d_in[25];
    const float* c3b = (const float*)d_in[26];
    float* out = (float*)d_out;

    float* hbuf;  cudaGetSymbolAddress((void**)&hbuf,  d_h);
    float* xbuf;  cudaGetSymbolAddress((void**)&xbuf,  d_xb);

    const int KDIM[3] = {64, DMF, DMF};
    const int THR = 256;

    for (int l = 0; l < 3; l++) {
        const float* xin = (l == 0) ? x : xbuf;

        dim3 ggrid(DMF / 128, (NN + 127) / 128);
        gemm_kernel<<<ggrid, 256>>>(xin, W[l], hbuf, NN, KDIM[l]);

        scores_kernel<<<NN, 128>>>(hbuf, AS[l], AD[l]);

        int eth = ET * NHEAD;
        edge_max_kernel<<<(eth + THR - 1) / THR, THR>>>(ei);
        edge_exp_kernel<<<(eth + THR - 1) / THR, THR>>>(ei);

        int nel = NN * DMF;
        init_agg_kernel<<<(nel + THR - 1) / THR, THR>>>(BB[l]);

        int agt = ET * 128;
        aggregate_kernel<<<(agt + THR - 1) / THR, THR>>>(ei);

        bn_zero_kernel<<<1, DMF>>>();
        bn_stats_kernel<<<(NN + 63) / 64, DMF>>>();
        bn_finalize_kernel<<<1, DMF>>>(GM[l], BE[l]);
        bn_apply_kernel<<<(nel + THR - 1) / THR, THR>>>();
    }

    int pil = GG * DMF;
    pool_init_kernel<<<(pil + THR - 1) / THR, THR>>>();
    pool_cnt_kernel<<<(NN + THR - 1) / THR, THR>>>(batch);
    int pft = NN * 128;
    pool_feat_kernel<<<(pft + THR - 1) / THR, THR>>>(batch);

    mlp1_kernel<<<GG, 128>>>(c1w, c1b);
    mlp2_kernel<<<GG, 64>>>(c2w, c2b);
    mlp3_kernel<<<(GG + 63) / 64, 64>>>(c3w, c3b, out);
}

// round 4
// speedup vs baseline: 1.4412x; 1.4412x over previous
#include <cuda_runtime.h>
#include <math.h>

#define NN    50000
#define EE    200000
#define ET    250000   // EE + NN self loops
#define GG    2000
#define DMF   512
#define NHEAD 4
#define HIDD  128
#define NEG_SLOPE 0.2f
#define BN_EPS 1e-5f

// ---------------- scratch (device globals; no allocation allowed) ----------
__device__ float d_h   [NN * DMF];     // h = x @ W  (per layer)
__device__ float d_xb  [NN * DMF];     // layer output / next layer input
__device__ float d_agg [NN * DMF];     // segment-sum accumulator (init = bias)
__device__ float d_ssrc[NN * NHEAD];
__device__ float d_sdst[NN * NHEAD];
__device__ float d_m   [NN * NHEAD];   // segment max
__device__ float d_den [NN * NHEAD];   // segment sum of exp
__device__ float d_ex  [ET * NHEAD];   // per-edge logits, then exp
__device__ float d_bnsum[DMF];
__device__ float d_bnss [DMF];
__device__ float d_scale[DMF];
__device__ float d_shift[DMF];
__device__ float d_gsum [GG * DMF];
__device__ int   d_gmaxi[GG * DMF];
__device__ float d_gcnt [GG];
__device__ float d_h1   [GG * 128];
__device__ float d_h2   [GG * 64];

// ---------------- helpers ----------------
__device__ __forceinline__ void redAddV4(float* p, float4 v) {
    asm volatile("red.global.add.v4.f32 [%0], {%1,%2,%3,%4};"
                 :: "l"(p), "f"(v.x), "f"(v.y), "f"(v.z), "f"(v.w) : "memory");
}

__device__ __forceinline__ void atomicMaxF(float* a, float v) {
    if (v >= 0.0f) atomicMax((int*)a, __float_as_int(v));
    else           atomicMin((unsigned int*)a, (unsigned int)__float_as_int(v));
}

__device__ __forceinline__ unsigned f2tf32(float x) {
    unsigned r;
    asm("cvt.rna.tf32.f32 %0, %1;" : "=r"(r) : "f"(x));
    return r;
}

// ---------------- TF32 tensor-core GEMM: C[M,512] = A[M,K] @ B[K,512] ------
// 128x128 block tile, BK=16, 256 threads (8 warps, 2x4), warp tile 64x32,
// m16n8k8 tf32 MMA. SMEM pitch 136 -> conflict-free fragment LDS.
#define SPITCH 136

__global__ void __launch_bounds__(256)
gemm_tf32_kernel(const float* __restrict__ A, const float* __restrict__ B,
                 float* __restrict__ C, int M, int K) {
    __shared__ unsigned As[16][SPITCH];
    __shared__ unsigned Bs[16][SPITCH];

    const int bx = blockIdx.x;   // N tile (0..3)
    const int by = blockIdx.y;   // M tile
    const int tid = threadIdx.x;
    const int warp = tid >> 5, lane = tid & 31;
    const int wr = warp & 1, wc = warp >> 1;      // 2 x 4 warp grid
    const int m0 = wr * 64, n0 = wc * 32;
    const int r = lane >> 2, c = lane & 3;        // groupID, tig

    float acc[4][4][4];
#pragma unroll
    for (int i = 0; i < 4; i++)
#pragma unroll
        for (int j = 0; j < 4; j++)
#pragma unroll
            for (int q = 0; q < 4; q++) acc[i][j][q] = 0.0f;

    for (int k0 = 0; k0 < K; k0 += 16) {
#pragma unroll
        for (int p = 0; p < 2; p++) {
            int f = tid + p * 256;               // 0..511
            int m = f & 127;
            int kq = (f >> 7) * 4;               // 0,4,8,12
            int gm = by * 128 + m;
            float4 v = make_float4(0.f, 0.f, 0.f, 0.f);
            if (gm < M) v = *(const float4*)(A + (long long)gm * K + k0 + kq);
            As[kq + 0][m] = f2tf32(v.x);
            As[kq + 1][m] = f2tf32(v.y);
            As[kq + 2][m] = f2tf32(v.z);
            As[kq + 3][m] = f2tf32(v.w);

            int kb = f >> 5;                     // 0..15
            int nq = (f & 31) * 4;
            float4 bv = *(const float4*)(B + (long long)(k0 + kb) * DMF + bx * 128 + nq);
            unsigned b0 = f2tf32(bv.x), b1 = f2tf32(bv.y);
            unsigned b2 = f2tf32(bv.z), b3 = f2tf32(bv.w);
            *(uint4*)&Bs[kb][nq] = make_uint4(b0, b1, b2, b3);
        }
        __syncthreads();

#pragma unroll
        for (int ks = 0; ks < 2; ks++) {
            const int kc = ks * 8;
            unsigned bf[4][2];
#pragma unroll
            for (int j = 0; j < 4; j++) {
                bf[j][0] = Bs[kc + c][n0 + j * 8 + r];
                bf[j][1] = Bs[kc + c + 4][n0 + j * 8 + r];
            }
#pragma unroll
            for (int i = 0; i < 4; i++) {
                unsigned a0 = As[kc + c][m0 + i * 16 + r];
                unsigned a1 = As[kc + c][m0 + i * 16 + r + 8];
                unsigned a2 = As[kc + c + 4][m0 + i * 16 + r];
                unsigned a3 = As[kc + c + 4][m0 + i * 16 + r + 8];
#pragma unroll
                for (int j = 0; j < 4; j++) {
                    asm volatile(
                        "mma.sync.aligned.m16n8k8.row.col.f32.tf32.tf32.f32 "
                        "{%0,%1,%2,%3},{%4,%5,%6,%7},{%8,%9},{%0,%1,%2,%3};\n"
                        : "+f"(acc[i][j][0]), "+f"(acc[i][j][1]),
                          "+f"(acc[i][j][2]), "+f"(acc[i][j][3])
                        : "r"(a0), "r"(a1), "r"(a2), "r"(a3),
                          "r"(bf[j][0]), "r"(bf[j][1]));
                }
            }
        }
        __syncthreads();
    }

#pragma unroll
    for (int i = 0; i < 4; i++) {
        int row0 = by * 128 + m0 + i * 16 + r;
#pragma unroll
        for (int j = 0; j < 4; j++) {
            int col = bx * 128 + n0 + j * 8 + 2 * c;
            if (row0 < M)
                *(float2*)(C + (long long)row0 * DMF + col) =
                    make_float2(acc[i][j][0], acc[i][j][1]);
            if (row0 + 8 < M)
                *(float2*)(C + (long long)(row0 + 8) * DMF + col) =
                    make_float2(acc[i][j][2], acc[i][j][3]);
        }
    }
}

// ---------------- attention scores + segment init ----------------
__global__ void scores_kernel(const float* __restrict__ h,
                              const float* __restrict__ as_,
                              const float* __restrict__ ad_) {
    int n = blockIdx.x;
    int warp = threadIdx.x >> 5, lane = threadIdx.x & 31;
    const float* hp  = h   + (long long)n * DMF + warp * HIDD;
    const float* asp = as_ + warp * HIDD;
    const float* adp = ad_ + warp * HIDD;
    float s1 = 0.f, s2 = 0.f;
#pragma unroll
    for (int i = 0; i < 4; i++) {
        float v = hp[lane + 32 * i];
        s1 += v * asp[lane + 32 * i];
        s2 += v * adp[lane + 32 * i];
    }
#pragma unroll
    for (int o = 16; o; o >>= 1) {
        s1 += __shfl_down_sync(0xffffffffu, s1, o);
        s2 += __shfl_down_sync(0xffffffffu, s2, o);
    }
    if (lane == 0) {
        d_ssrc[n * NHEAD + warp] = s1;
        d_sdst[n * NHEAD + warp] = s2;
        d_m  [n * NHEAD + warp] = -1e30f;
        d_den[n * NHEAD + warp] = 0.f;
    }
}

// ---------------- edge pass 1: logits + segment max ----------------
__global__ void edge_max_kernel(const int* __restrict__ ei) {
    int idx = blockIdx.x * blockDim.x + threadIdx.x;
    if (idx >= ET * NHEAD) return;
    int e = idx >> 2, h = idx & 3;
    int s, d;
    if (e < EE) { s = ei[e]; d = ei[EE + e]; } else { s = d = e - EE; }
    float v = d_ssrc[s * NHEAD + h] + d_sdst[d * NHEAD + h];
    v = (v > 0.f) ? v : NEG_SLOPE * v;
    d_ex[idx] = v;
    atomicMaxF(&d_m[d * NHEAD + h], v);
}

// ---------------- edge pass 2: exp + segment sum ----------------
__global__ void edge_exp_kernel(const int* __restrict__ ei) {
    int idx = blockIdx.x * blockDim.x + threadIdx.x;
    if (idx >= ET * NHEAD) return;
    int e = idx >> 2, h = idx & 3;
    int d;
    if (e < EE) d = ei[EE + e]; else d = e - EE;
    float ex = expf(d_ex[idx] - d_m[d * NHEAD + h]);
    d_ex[idx] = ex;
    atomicAdd(&d_den[d * NHEAD + h], ex);
}

// ---------------- init accumulator with bias ----------------
__global__ void init_agg_kernel(const float* __restrict__ bias) {
    int i = blockIdx.x * blockDim.x + threadIdx.x;
    if (i < NN * DMF) d_agg[i] = bias[i & (DMF - 1)];
}

// ---------------- weighted scatter aggregation ----------------
__global__ void aggregate_kernel(const int* __restrict__ ei) {
    int i = blockIdx.x * blockDim.x + threadIdx.x;
    if (i >= ET * 128) return;              // 128 float4 lanes per edge
    int e = i >> 7, j = i & 127;
    int head = j >> 5;
    int s, d;
    if (e < EE) { s = ei[e]; d = ei[EE + e]; } else { s = d = e - EE; }
    float alpha = d_ex[e * NHEAD + head] / d_den[d * NHEAD + head];
    float4 hv = *(const float4*)(d_h + (long long)s * DMF + j * 4);
    hv.x *= alpha; hv.y *= alpha; hv.z *= alpha; hv.w *= alpha;
    redAddV4(d_agg + (long long)d * DMF + j * 4, hv);
}

// ---------------- batch norm ----------------
__global__ void bn_zero_kernel() {
    int c = threadIdx.x;
    d_bnsum[c] = 0.f; d_bnss[c] = 0.f;
}

__global__ void __launch_bounds__(512)
bn_stats_kernel() {
    int c = threadIdx.x;
    int r0 = blockIdx.x * 64;
    int rend = min(r0 + 64, NN);
    float s = 0.f, ss = 0.f;
    for (int r = r0; r < rend; r++) {
        float v = d_agg[(long long)r * DMF + c];
        s += v; ss += v * v;
    }
    atomicAdd(&d_bnsum[c], s);
    atomicAdd(&d_bnss[c], ss);
}

__global__ void bn_finalize_kernel(const float* __restrict__ g,
                                   const float* __restrict__ be) {
    int c = threadIdx.x;
    float mean = d_bnsum[c] * (1.0f / NN);
    float var  = d_bnss[c] * (1.0f / NN) - mean * mean;
    float sc = g[c] * rsqrtf(var + BN_EPS);
    d_scale[c] = sc;
    d_shift[c] = be[c] - mean * sc;
}

__global__ void bn_apply_kernel() {
    int i = blockIdx.x * blockDim.x + threadIdx.x;
    if (i >= NN * DMF) return;
    int c = i & (DMF - 1);
    float v = d_agg[i] * d_scale[c] + d_shift[c];
    d_xb[i] = fmaxf(v, 0.f);
}

// ---------------- pooling ----------------
__global__ void pool_init_kernel() {
    int i = blockIdx.x * blockDim.x + threadIdx.x;
    if (i < GG * DMF) { d_gsum[i] = 0.f; d_gmaxi[i] = 0; }
    if (i < GG) d_gcnt[i] = 0.f;
}

__global__ void pool_cnt_kernel(const int* __restrict__ batch) {
    int n = blockIdx.x * blockDim.x + threadIdx.x;
    if (n < NN) atomicAdd(&d_gcnt[batch[n]], 1.0f);
}

__global__ void pool_feat_kernel(const int* __restrict__ batch) {
    int i = blockIdx.x * blockDim.x + threadIdx.x;
    if (i >= NN * 128) return;              // float4 lanes
    int n = i >> 7, c4 = i & 127;
    int g = batch[n];
    float4 v = *(const float4*)(d_xb + (long long)n * DMF + c4 * 4);
    redAddV4(d_gsum + (long long)g * DMF + c4 * 4, v);
    int* mp = d_gmaxi + (long long)g * DMF + c4 * 4;
    atomicMax(mp + 0, __float_as_int(v.x));   // values >= 0 after ReLU
    atomicMax(mp + 1, __float_as_int(v.y));
    atomicMax(mp + 2, __float_as_int(v.z));
    atomicMax(mp + 3, __float_as_int(v.w));
}

// ---------------- graph-level MLP ----------------
__global__ void __launch_bounds__(128)
mlp1_kernel(const float* __restrict__ c1w, const float* __restrict__ c1b) {
    __shared__ float hrow[1024];
    int g = blockIdx.x, t = threadIdx.x;
    float cnt = fmaxf(d_gcnt[g], 1.0f);
    float inv = 1.0f / cnt;
    for (int c = t; c < DMF; c += 128) {
        hrow[c]       = d_gsum[g * DMF + c] * inv;
        hrow[DMF + c] = __int_as_float(d_gmaxi[g * DMF + c]);
    }
    __syncthreads();
    float acc = c1b[t];
    for (int k = 0; k < 1024; k++) acc = fmaf(hrow[k], c1w[k * 128 + t], acc);
    d_h1[g * 128 + t] = fmaxf(acc, 0.f);
}

__global__ void __launch_bounds__(64)
mlp2_kernel(const float* __restrict__ c2w, const float* __restrict__ c2b) {
    __shared__ float hrow[128];
    int g = blockIdx.x, t = threadIdx.x;
    for (int c = t; c < 128; c += 64) hrow[c] = d_h1[g * 128 + c];
    __syncthreads();
    float acc = c2b[t];
    for (int k = 0; k < 128; k++) acc = fmaf(hrow[k], c2w[k * 64 + t], acc);
    d_h2[g * 64 + t] = fmaxf(acc, 0.f);
}

__global__ void mlp3_kernel(const float* __restrict__ c3w,
                            const float* __restrict__ c3b,
                            float* __restrict__ out) {
    int g = blockIdx.x * blockDim.x + threadIdx.x;
    if (g >= GG) return;
    float acc = c3b[0];
    for (int k = 0; k < 64; k++) acc = fmaf(d_h2[g * 64 + k], c3w[k], acc);
    out[g] = 1.0f / (1.0f + expf(-acc));
}

// ---------------- launch ----------------
extern "C" void kernel_launch(void* const* d_in, const int* in_sizes, int n_in,
                              void* d_out, int out_size) {
    const float* x     = (const float*)d_in[0];
    const int*   ei    = (const int*)  d_in[1];
    const int*   batch = (const int*)  d_in[2];

    const float* W [3] = {(const float*)d_in[3],  (const float*)d_in[9],  (const float*)d_in[15]};
    const float* AS[3] = {(const float*)d_in[4],  (const float*)d_in[10], (const float*)d_in[16]};
    const float* AD[3] = {(const float*)d_in[5],  (const float*)d_in[11], (const float*)d_in[17]};
    const float* BB[3] = {(const float*)d_in[6],  (const float*)d_in[12], (const float*)d_in[18]};
    const float* GM[3] = {(const float*)d_in[7],  (const float*)d_in[13], (const float*)d_in[19]};
    const float* BE[3] = {(const float*)d_in[8],  (const float*)d_in[14], (const float*)d_in[20]};

    const float* c1w = (const float*)d_in[21];
    const float* c1b = (const float*)d_in[22];
    const float* c2w = (const float*)d_in[23];
    const float* c2b = (const float*)d_in[24];
    const float* c3w = (const float*)d_in[25];
    const float* c3b = (const float*)d_in[26];
    float* out = (float*)d_out;

    float* hbuf;  cudaGetSymbolAddress((void**)&hbuf,  d_h);
    float* xbuf;  cudaGetSymbolAddress((void**)&xbuf,  d_xb);

    const int KDIM[3] = {64, DMF, DMF};
    const int THR = 256;

    for (int l = 0; l < 3; l++) {
        const float* xin = (l == 0) ? x : xbuf;

        dim3 ggrid(DMF / 128, (NN + 127) / 128);
        gemm_tf32_kernel<<<ggrid, 256>>>(xin, W[l], hbuf, NN, KDIM[l]);

        scores_kernel<<<NN, 128>>>(hbuf, AS[l], AD[l]);

        int eth = ET * NHEAD;
        edge_max_kernel<<<(eth + THR - 1) / THR, THR>>>(ei);
        edge_exp_kernel<<<(eth + THR - 1) / THR, THR>>>(ei);

        int nel = NN * DMF;
        init_agg_kernel<<<(nel + THR - 1) / THR, THR>>>(BB[l]);

        int agt = ET * 128;
        aggregate_kernel<<<(agt + THR - 1) / THR, THR>>>(ei);

        bn_zero_kernel<<<1, DMF>>>();
        bn_stats_kernel<<<(NN + 63) / 64, DMF>>>();
        bn_finalize_kernel<<<1, DMF>>>(GM[l], BE[l]);
        bn_apply_kernel<<<(nel + THR - 1) / THR, THR>>>();
    }

    int pil = GG * DMF;
    pool_init_kernel<<<(pil + THR - 1) / THR, THR>>>();
    pool_cnt_kernel<<<(NN + THR - 1) / THR, THR>>>(batch);
    int pft = NN * 128;
    pool_feat_kernel<<<(pft + THR - 1) / THR, THR>>>(batch);

    mlp1_kernel<<<GG, 128>>>(c1w, c1b);
    mlp2_kernel<<<GG, 64>>>(c2w, c2b);
    mlp3_kernel<<<(GG + 63) / 64, 64>>>(c3w, c3b, out);
}

// round 5
// speedup vs baseline: 2.1237x; 1.4736x over previous
#include <cuda_runtime.h>
#include <math.h>

#define NN    50000
#define EE    200000
#define ET    250000   // EE + NN self loops
#define GG    2000
#define DMF   512
#define NHEAD 4
#define HIDD  128
#define NEG_SLOPE 0.2f
#define BN_EPS 1e-5f

// ---------------- scratch (device globals; no allocation allowed) ----------
__device__ float d_h   [NN * DMF];     // h = x @ W  (per layer)
__device__ float d_xb  [NN * DMF];     // layer output / next layer input
__device__ float d_agg [NN * DMF];     // aggregated output (bias folded)
__device__ float d_ssrc[NN * NHEAD];
__device__ float d_sdst[NN * NHEAD];
__device__ float d_m   [NN * NHEAD];   // segment max
__device__ float d_den [NN * NHEAD];   // segment sum of exp
__device__ float d_ex  [ET * NHEAD];   // per-edge logits, then exp
__device__ float d_bnsum[DMF];
__device__ float d_bnss [DMF];
__device__ float d_scale[DMF];
__device__ float d_shift[DMF];
__device__ float d_gsum [GG * DMF];
__device__ int   d_gmaxi[GG * DMF];
__device__ float d_gcnt [GG];
__device__ float d_h1   [GG * 128];
__device__ float d_h2   [GG * 64];
// CSR (rebuilt each launch; edge structure constant across the 3 layers)
__device__ int   d_deg   [NN];
__device__ int   d_rowptr[NN];
__device__ int   d_cursor[NN];
__device__ int   d_eid   [ET];

// ---------------- helpers ----------------
__device__ __forceinline__ void redAddV4(float* p, float4 v) {
    asm volatile("red.global.add.v4.f32 [%0], {%1,%2,%3,%4};"
                 :: "l"(p), "f"(v.x), "f"(v.y), "f"(v.z), "f"(v.w) : "memory");
}

__device__ __forceinline__ void atomicMaxF(float* a, float v) {
    if (v >= 0.0f) atomicMax((int*)a, __float_as_int(v));
    else           atomicMin((unsigned int*)a, (unsigned int)__float_as_int(v));
}

__device__ __forceinline__ void cpAsync16(void* smem_dst, const void* gsrc, int src_sz) {
    unsigned d = (unsigned)__cvta_generic_to_shared(smem_dst);
    asm volatile("cp.async.cg.shared.global [%0], [%1], 16, %2;"
                 :: "r"(d), "l"(gsrc), "r"(src_sz));
}

// ---------------- TF32 tensor-core GEMM, 2-stage cp.async pipeline --------
// C[M,512] = A[M,K] @ B[K,512]. 128x128 tile, BK=16, 256 threads (8 warps,
// 2x4), warp tile 64x32, m16n8k8. A smem [m][k] pitch 20; B smem [k][n]
// pitch 136 (both verified conflict-free for the fragment LDS patterns).
#define APITCH 20
#define BPITCH 136

__global__ void __launch_bounds__(256)
gemm_tf32_kernel(const float* __restrict__ A, const float* __restrict__ B,
                 float* __restrict__ C, int M, int K) {
    __shared__ float As[2][128 * APITCH];
    __shared__ float Bs[2][16 * BPITCH];

    const int bx = blockIdx.x;   // N tile (0..3)
    const int by = blockIdx.y;   // M tile
    const int tid = threadIdx.x;
    const int warp = tid >> 5, lane = tid & 31;
    const int wr = warp & 1, wc = warp >> 1;      // 2 x 4 warp grid
    const int m0 = wr * 64, n0 = wc * 32;
    const int r = lane >> 2, c = lane & 3;

    float acc[4][4][4];
#pragma unroll
    for (int i = 0; i < 4; i++)
#pragma unroll
        for (int j = 0; j < 4; j++)
#pragma unroll
            for (int q = 0; q < 4; q++) acc[i][j][q] = 0.0f;

    const int KT = K >> 4;

    // tile loader: A 2 chunks/thread, B 2 chunks/thread (16B each)
    auto load_tile = [&](int st, int k0) {
#pragma unroll
        for (int p = 0; p < 2; p++) {
            int f = tid + p * 256;               // 0..511
            int m = f >> 2, ch = (f & 3) * 4;
            int gm = by * 128 + m;
            cpAsync16(&As[st][m * APITCH + ch],
                      A + (long long)gm * K + k0 + ch,
                      (gm < M) ? 16 : 0);
        }
#pragma unroll
        for (int p = 0; p < 2; p++) {
            int f = tid + p * 256;
            int kb = f >> 5, ch = (f & 31) * 4;
            cpAsync16(&Bs[st][kb * BPITCH + ch],
                      B + (long long)(k0 + kb) * DMF + bx * 128 + ch,
                      16);
        }
    };

    load_tile(0, 0);
    asm volatile("cp.async.commit_group;");

    for (int kt = 0; kt < KT; kt++) {
        const int st = kt & 1;
        if (kt + 1 < KT) load_tile(st ^ 1, (kt + 1) * 16);
        asm volatile("cp.async.commit_group;");
        asm volatile("cp.async.wait_group 1;");
        __syncthreads();

        const unsigned* Au = (const unsigned*)As[st];
        const unsigned* Bu = (const unsigned*)Bs[st];
#pragma unroll
        for (int ks = 0; ks < 2; ks++) {
            const int kc = ks * 8;
            unsigned bf[4][2];
#pragma unroll
            for (int j = 0; j < 4; j++) {
                bf[j][0] = Bu[(kc + c) * BPITCH + n0 + j * 8 + r];
                bf[j][1] = Bu[(kc + c + 4) * BPITCH + n0 + j * 8 + r];
            }
#pragma unroll
            for (int i = 0; i < 4; i++) {
                unsigned a0 = Au[(m0 + i * 16 + r)     * APITCH + kc + c];
                unsigned a1 = Au[(m0 + i * 16 + r + 8) * APITCH + kc + c];
                unsigned a2 = Au[(m0 + i * 16 + r)     * APITCH + kc + c + 4];
                unsigned a3 = Au[(m0 + i * 16 + r + 8) * APITCH + kc + c + 4];
#pragma unroll
                for (int j = 0; j < 4; j++) {
                    asm volatile(
                        "mma.sync.aligned.m16n8k8.row.col.f32.tf32.tf32.f32 "
                        "{%0,%1,%2,%3},{%4,%5,%6,%7},{%8,%9},{%0,%1,%2,%3};\n"
                        : "+f"(acc[i][j][0]), "+f"(acc[i][j][1]),
                          "+f"(acc[i][j][2]), "+f"(acc[i][j][3])
                        : "r"(a0), "r"(a1), "r"(a2), "r"(a3),
                          "r"(bf[j][0]), "r"(bf[j][1]));
                }
            }
        }
        __syncthreads();
    }

#pragma unroll
    for (int i = 0; i < 4; i++) {
        int row0 = by * 128 + m0 + i * 16 + r;
#pragma unroll
        for (int j = 0; j < 4; j++) {
            int col = bx * 128 + n0 + j * 8 + 2 * c;
            if (row0 < M)
                *(float2*)(C + (long long)row0 * DMF + col) =
                    make_float2(acc[i][j][0], acc[i][j][1]);
            if (row0 + 8 < M)
                *(float2*)(C + (long long)(row0 + 8) * DMF + col) =
                    make_float2(acc[i][j][2], acc[i][j][3]);
        }
    }
}

// ---------------- CSR build (once per launch) ----------------
__global__ void zero_deg_kernel() {
    int n = blockIdx.x * blockDim.x + threadIdx.x;
    if (n < NN) d_deg[n] = 0;
}

__global__ void count_deg_kernel(const int* __restrict__ ei) {
    int e = blockIdx.x * blockDim.x + threadIdx.x;
    if (e >= ET) return;
    int dst = (e < EE) ? ei[EE + e] : e - EE;
    atomicAdd(&d_deg[dst], 1);
}

__global__ void __launch_bounds__(1024)
scan_kernel() {
    __shared__ int partial[1024];
    const int C = (NN + 1023) / 1024;       // 49
    int t = threadIdx.x;
    int lo = t * C, hi = min(lo + C, NN);
    int s = 0;
    for (int i = lo; i < hi; i++) s += d_deg[i];
    partial[t] = s;
    __syncthreads();
    for (int off = 1; off < 1024; off <<= 1) {
        int v = partial[t];
        int add = (t >= off) ? partial[t - off] : 0;
        __syncthreads();
        partial[t] = v + add;
        __syncthreads();
    }
    int run = (t == 0) ? 0 : partial[t - 1];
    for (int i = lo; i < hi; i++) {
        d_rowptr[i] = run;
        d_cursor[i] = run;
        run += d_deg[i];
    }
}

__global__ void scatter_kernel(const int* __restrict__ ei) {
    int e = blockIdx.x * blockDim.x + threadIdx.x;
    if (e >= ET) return;
    int dst = (e < EE) ? ei[EE + e] : e - EE;
    int pos = atomicAdd(&d_cursor[dst], 1);
    d_eid[pos] = e;
}

// ---------------- attention scores + segment init ----------------
__global__ void scores_kernel(const float* __restrict__ h,
                              const float* __restrict__ as_,
                              const float* __restrict__ ad_) {
    int n = blockIdx.x;
    int warp = threadIdx.x >> 5, lane = threadIdx.x & 31;
    const float* hp  = h   + (long long)n * DMF + warp * HIDD;
    const float* asp = as_ + warp * HIDD;
    const float* adp = ad_ + warp * HIDD;
    float s1 = 0.f, s2 = 0.f;
#pragma unroll
    for (int i = 0; i < 4; i++) {
        float v = hp[lane + 32 * i];
        s1 += v * asp[lane + 32 * i];
        s2 += v * adp[lane + 32 * i];
    }
#pragma unroll
    for (int o = 16; o; o >>= 1) {
        s1 += __shfl_down_sync(0xffffffffu, s1, o);
        s2 += __shfl_down_sync(0xffffffffu, s2, o);
    }
    if (lane == 0) {
        d_ssrc[n * NHEAD + warp] = s1;
        d_sdst[n * NHEAD + warp] = s2;
        d_m  [n * NHEAD + warp] = -1e30f;
        d_den[n * NHEAD + warp] = 0.f;
    }
}

// ---------------- edge pass 1: logits + segment max ----------------
__global__ void edge_max_kernel(const int* __restrict__ ei) {
    int idx = blockIdx.x * blockDim.x + threadIdx.x;
    if (idx >= ET * NHEAD) return;
    int e = idx >> 2, h = idx & 3;
    int s, d;
    if (e < EE) { s = ei[e]; d = ei[EE + e]; } else { s = d = e - EE; }
    float v = d_ssrc[s * NHEAD + h] + d_sdst[d * NHEAD + h];
    v = (v > 0.f) ? v : NEG_SLOPE * v;
    d_ex[idx] = v;
    atomicMaxF(&d_m[d * NHEAD + h], v);
}

// ---------------- edge pass 2: exp + segment sum ----------------
__global__ void edge_exp_kernel(const int* __restrict__ ei) {
    int idx = blockIdx.x * blockDim.x + threadIdx.x;
    if (idx >= ET * NHEAD) return;
    int e = idx >> 2, h = idx & 3;
    int d;
    if (e < EE) d = ei[EE + e]; else d = e - EE;
    float ex = expf(d_ex[idx] - d_m[d * NHEAD + h]);
    d_ex[idx] = ex;
    atomicAdd(&d_den[d * NHEAD + h], ex);
}

// ---------------- CSR gather aggregation (bias folded, no atomics) --------
__global__ void __launch_bounds__(128)
aggregate_csr_kernel(const int* __restrict__ ei,
                     const float* __restrict__ bias) {
    __shared__ int   sm_src[128];
    __shared__ float sm_alpha[NHEAD][128];

    const int n = blockIdx.x;
    const int t = threadIdx.x;
    const int w = t >> 5;                 // warp == head for alpha reads

    const int start = d_rowptr[n];
    const int deg   = d_deg[n];

    // reciprocal denominators for this dst (4 heads)
    float4 den = *(const float4*)(d_den + n * NHEAD);
    float rd0 = 1.0f / den.x, rd1 = 1.0f / den.y;
    float rd2 = 1.0f / den.z, rd3 = 1.0f / den.w;

    float4 acc = make_float4(0.f, 0.f, 0.f, 0.f);

    for (int base = 0; base < deg; base += 128) {
        int cnt = min(128, deg - base);
        if (t < cnt) {
            int e = d_eid[start + base + t];
            sm_src[t] = (e < EE) ? ei[e] : e - EE;
            float4 ex = *(const float4*)(d_ex + e * NHEAD);
            sm_alpha[0][t] = ex.x * rd0;
            sm_alpha[1][t] = ex.y * rd1;
            sm_alpha[2][t] = ex.z * rd2;
            sm_alpha[3][t] = ex.w * rd3;
        }
        __syncthreads();
#pragma unroll 2
        for (int i = 0; i < cnt; i++) {
            int s = sm_src[i];
            float alpha = sm_alpha[w][i];
            float4 hv = *(const float4*)(d_h + (long long)s * DMF + t * 4);
            acc.x = fmaf(alpha, hv.x, acc.x);
            acc.y = fmaf(alpha, hv.y, acc.y);
            acc.z = fmaf(alpha, hv.z, acc.z);
            acc.w = fmaf(alpha, hv.w, acc.w);
        }
        __syncthreads();
    }

    float4 b = *(const float4*)(bias + t * 4);
    acc.x += b.x; acc.y += b.y; acc.z += b.z; acc.w += b.w;
    *(float4*)(d_agg + (long long)n * DMF + t * 4) = acc;
}

// ---------------- batch norm ----------------
__global__ void bn_zero_kernel() {
    int c = threadIdx.x;
    d_bnsum[c] = 0.f; d_bnss[c] = 0.f;
}

__global__ void __launch_bounds__(512)
bn_stats_kernel() {
    int c = threadIdx.x;
    int r0 = blockIdx.x * 64;
    int rend = min(r0 + 64, NN);
    float s = 0.f, ss = 0.f;
    for (int r = r0; r < rend; r++) {
        float v = d_agg[(long long)r * DMF + c];
        s += v; ss += v * v;
    }
    atomicAdd(&d_bnsum[c], s);
    atomicAdd(&d_bnss[c], ss);
}

__global__ void bn_finalize_kernel(const float* __restrict__ g,
                                   const float* __restrict__ be) {
    int c = threadIdx.x;
    float mean = d_bnsum[c] * (1.0f / NN);
    float var  = d_bnss[c] * (1.0f / NN) - mean * mean;
    float sc = g[c] * rsqrtf(var + BN_EPS);
    d_scale[c] = sc;
    d_shift[c] = be[c] - mean * sc;
}

__global__ void bn_apply_kernel() {
    int i = blockIdx.x * blockDim.x + threadIdx.x;
    if (i >= NN * DMF) return;
    int c = i & (DMF - 1);
    float v = d_agg[i] * d_scale[c] + d_shift[c];
    d_xb[i] = fmaxf(v, 0.f);
}

// ---------------- pooling ----------------
__global__ void pool_init_kernel() {
    int i = blockIdx.x * blockDim.x + threadIdx.x;
    if (i < GG * DMF) { d_gsum[i] = 0.f; d_gmaxi[i] = 0; }
    if (i < GG) d_gcnt[i] = 0.f;
}

__global__ void pool_cnt_kernel(const int* __restrict__ batch) {
    int n = blockIdx.x * blockDim.x + threadIdx.x;
    if (n < NN) atomicAdd(&d_gcnt[batch[n]], 1.0f);
}

__global__ void pool_feat_kernel(const int* __restrict__ batch) {
    int i = blockIdx.x * blockDim.x + threadIdx.x;
    if (i >= NN * 128) return;              // float4 lanes
    int n = i >> 7, c4 = i & 127;
    int g = batch[n];
    float4 v = *(const float4*)(d_xb + (long long)n * DMF + c4 * 4);
    redAddV4(d_gsum + (long long)g * DMF + c4 * 4, v);
    int* mp = d_gmaxi + (long long)g * DMF + c4 * 4;
    atomicMax(mp + 0, __float_as_int(v.x));   // values >= 0 after ReLU
    atomicMax(mp + 1, __float_as_int(v.y));
    atomicMax(mp + 2, __float_as_int(v.z));
    atomicMax(mp + 3, __float_as_int(v.w));
}

// ---------------- graph-level MLP ----------------
__global__ void __launch_bounds__(128)
mlp1_kernel(const float* __restrict__ c1w, const float* __restrict__ c1b) {
    __shared__ float hrow[1024];
    int g = blockIdx.x, t = threadIdx.x;
    float cnt = fmaxf(d_gcnt[g], 1.0f);
    float inv = 1.0f / cnt;
    for (int c = t; c < DMF; c += 128) {
        hrow[c]       = d_gsum[g * DMF + c] * inv;
        hrow[DMF + c] = __int_as_float(d_gmaxi[g * DMF + c]);
    }
    __syncthreads();
    float acc = c1b[t];
    for (int k = 0; k < 1024; k++) acc = fmaf(hrow[k], c1w[k * 128 + t], acc);
    d_h1[g * 128 + t] = fmaxf(acc, 0.f);
}

__global__ void __launch_bounds__(64)
mlp2_kernel(const float* __restrict__ c2w, const float* __restrict__ c2b) {
    __shared__ float hrow[128];
    int g = blockIdx.x, t = threadIdx.x;
    for (int c = t; c < 128; c += 64) hrow[c] = d_h1[g * 128 + c];
    __syncthreads();
    float acc = c2b[t];
    for (int k = 0; k < 128; k++) acc = fmaf(hrow[k], c2w[k * 64 + t], acc);
    d_h2[g * 64 + t] = fmaxf(acc, 0.f);
}

__global__ void mlp3_kernel(const float* __restrict__ c3w,
                            const float* __restrict__ c3b,
                            float* __restrict__ out) {
    int g = blockIdx.x * blockDim.x + threadIdx.x;
    if (g >= GG) return;
    float acc = c3b[0];
    for (int k = 0; k < 64; k++) acc = fmaf(d_h2[g * 64 + k], c3w[k], acc);
    out[g] = 1.0f / (1.0f + expf(-acc));
}

// ---------------- launch ----------------
extern "C" void kernel_launch(void* const* d_in, const int* in_sizes, int n_in,
                              void* d_out, int out_size) {
    const float* x     = (const float*)d_in[0];
    const int*   ei    = (const int*)  d_in[1];
    const int*   batch = (const int*)  d_in[2];

    const float* W [3] = {(const float*)d_in[3],  (const float*)d_in[9],  (const float*)d_in[15]};
    const float* AS[3] = {(const float*)d_in[4],  (const float*)d_in[10], (const float*)d_in[16]};
    const float* AD[3] = {(const float*)d_in[5],  (const float*)d_in[11], (const float*)d_in[17]};
    const float* BB[3] = {(const float*)d_in[6],  (const float*)d_in[12], (const float*)d_in[18]};
    const float* GM[3] = {(const float*)d_in[7],  (const float*)d_in[13], (const float*)d_in[19]};
    const float* BE[3] = {(const float*)d_in[8],  (const float*)d_in[14], (const float*)d_in[20]};

    const float* c1w = (const float*)d_in[21];
    const float* c1b = (const float*)d_in[22];
    const float* c2w = (const float*)d_in[23];
    const float* c2b = (const float*)d_in[24];
    const float* c3w = (const float*)d_in[25];
    const float* c3b = (const float*)d_in[26];
    float* out = (float*)d_out;

    float* hbuf;  cudaGetSymbolAddress((void**)&hbuf,  d_h);
    float* xbuf;  cudaGetSymbolAddress((void**)&xbuf,  d_xb);

    const int KDIM[3] = {64, DMF, DMF};
    const int THR = 256;

    // ---- CSR build (edge structure constant across layers) ----
    zero_deg_kernel<<<(NN + THR - 1) / THR, THR>>>();
    count_deg_kernel<<<(ET + THR - 1) / THR, THR>>>(ei);
    scan_kernel<<<1, 1024>>>();
    scatter_kernel<<<(ET + THR - 1) / THR, THR>>>(ei);

    for (int l = 0; l < 3; l++) {
        const float* xin = (l == 0) ? x : xbuf;

        dim3 ggrid(DMF / 128, (NN + 127) / 128);
        gemm_tf32_kernel<<<ggrid, 256>>>(xin, W[l], hbuf, NN, KDIM[l]);

        scores_kernel<<<NN, 128>>>(hbuf, AS[l], AD[l]);

        int eth = ET * NHEAD;
        edge_max_kernel<<<(eth + THR - 1) / THR, THR>>>(ei);
        edge_exp_kernel<<<(eth + THR - 1) / THR, THR>>>(ei);

        aggregate_csr_kernel<<<NN, 128>>>(ei, BB[l]);

        bn_zero_kernel<<<1, DMF>>>();
        bn_stats_kernel<<<(NN + 63) / 64, DMF>>>();
        bn_finalize_kernel<<<1, DMF>>>(GM[l], BE[l]);
        int nel = NN * DMF;
        bn_apply_kernel<<<(nel + THR - 1) / THR, THR>>>();
    }

    int pil = GG * DMF;
    pool_init_kernel<<<(pil + THR - 1) / THR, THR>>>();
    pool_cnt_kernel<<<(NN + THR - 1) / THR, THR>>>(batch);
    int pft = NN * 128;
    pool_feat_kernel<<<(pft + THR - 1) / THR, THR>>>(batch);

    mlp1_kernel<<<GG, 128>>>(c1w, c1b);
    mlp2_kernel<<<GG, 64>>>(c2w, c2b);
    mlp3_kernel<<<(GG + 63) / 64, 64>>>(c3w, c3b, out);
}

// round 6
// speedup vs baseline: 2.2381x; 1.0538x over previous
#include <cuda_runtime.h>
#include <math.h>

#define NN    50000
#define EE    200000
#define ET    250000   // EE + NN self loops
#define GG    2000
#define DMF   512
#define NHEAD 4
#define HIDD  128
#define NEG_SLOPE 0.2f
#define BN_EPS 1e-5f

// ---------------- scratch (device globals; no allocation allowed) ----------
__device__ float d_h   [NN * DMF];     // h = x @ W  (per layer)
__device__ float d_xb  [NN * DMF];     // layer output / next layer input
__device__ float d_agg [NN * DMF];     // aggregated output (bias folded)
__device__ float d_ssrc[NN * NHEAD];
__device__ float d_sdst[NN * NHEAD];
__device__ float d_bnsum[DMF];
__device__ float d_bnss [DMF];
__device__ float d_scale[DMF];
__device__ float d_shift[DMF];
__device__ float d_gsum [GG * DMF];
__device__ int   d_gmaxi[GG * DMF];
__device__ float d_gcnt [GG];
__device__ float d_h1   [GG * 128];
__device__ float d_h2   [GG * 64];
// CSR (rebuilt each launch; edge structure constant across the 3 layers)
__device__ int   d_deg   [NN];
__device__ int   d_rowptr[NN];
__device__ int   d_cursor[NN];
__device__ int   d_eid   [ET];

// ---------------- helpers ----------------
__device__ __forceinline__ void redAddV4(float* p, float4 v) {
    asm volatile("red.global.add.v4.f32 [%0], {%1,%2,%3,%4};"
                 :: "l"(p), "f"(v.x), "f"(v.y), "f"(v.z), "f"(v.w) : "memory");
}

__device__ __forceinline__ void cpAsync16(void* smem_dst, const void* gsrc, int src_sz) {
    unsigned d = (unsigned)__cvta_generic_to_shared(smem_dst);
    asm volatile("cp.async.cg.shared.global [%0], [%1], 16, %2;"
                 :: "r"(d), "l"(gsrc), "r"(src_sz));
}

__device__ __forceinline__ float leakyf(float v) {
    return (v > 0.f) ? v : NEG_SLOPE * v;
}

// ---------------- TF32 GEMM + fused attention-score epilogue --------------
// C[M,512] = A[M,K] @ B[K,512]; also s_src/s_dst partial dots (head == bx).
#define APITCH 20
#define BPITCH 136

__global__ void __launch_bounds__(256)
gemm_tf32_kernel(const float* __restrict__ A, const float* __restrict__ B,
                 float* __restrict__ C, int M, int K,
                 const float* __restrict__ a_s, const float* __restrict__ a_d) {
    __shared__ float As[2][128 * APITCH];
    __shared__ float Bs[2][16 * BPITCH];

    const int bx = blockIdx.x;   // N tile == head (0..3)
    const int by = blockIdx.y;   // M tile
    const int tid = threadIdx.x;
    const int warp = tid >> 5, lane = tid & 31;
    const int wr = warp & 1, wc = warp >> 1;      // 2 x 4 warp grid
    const int m0 = wr * 64, n0 = wc * 32;
    const int r = lane >> 2, c = lane & 3;

    float acc[4][4][4];
#pragma unroll
    for (int i = 0; i < 4; i++)
#pragma unroll
        for (int j = 0; j < 4; j++)
#pragma unroll
            for (int q = 0; q < 4; q++) acc[i][j][q] = 0.0f;

    const int KT = K >> 4;

    auto load_tile = [&](int st, int k0) {
#pragma unroll
        for (int p = 0; p < 2; p++) {
            int f = tid + p * 256;               // 0..511
            int m = f >> 2, ch = (f & 3) * 4;
            int gm = by * 128 + m;
            cpAsync16(&As[st][m * APITCH + ch],
                      A + (long long)gm * K + k0 + ch,
                      (gm < M) ? 16 : 0);
        }
#pragma unroll
        for (int p = 0; p < 2; p++) {
            int f = tid + p * 256;
            int kb = f >> 5, ch = (f & 31) * 4;
            cpAsync16(&Bs[st][kb * BPITCH + ch],
                      B + (long long)(k0 + kb) * DMF + bx * 128 + ch,
                      16);
        }
    };

    load_tile(0, 0);
    asm volatile("cp.async.commit_group;");

    for (int kt = 0; kt < KT; kt++) {
        const int st = kt & 1;
        if (kt + 1 < KT) load_tile(st ^ 1, (kt + 1) * 16);
        asm volatile("cp.async.commit_group;");
        asm volatile("cp.async.wait_group 1;");
        __syncthreads();

        const unsigned* Au = (const unsigned*)As[st];
        const unsigned* Bu = (const unsigned*)Bs[st];
#pragma unroll
        for (int ks = 0; ks < 2; ks++) {
            const int kc = ks * 8;
            unsigned bf[4][2];
#pragma unroll
            for (int j = 0; j < 4; j++) {
                bf[j][0] = Bu[(kc + c) * BPITCH + n0 + j * 8 + r];
                bf[j][1] = Bu[(kc + c + 4) * BPITCH + n0 + j * 8 + r];
            }
#pragma unroll
            for (int i = 0; i < 4; i++) {
                unsigned a0 = Au[(m0 + i * 16 + r)     * APITCH + kc + c];
                unsigned a1 = Au[(m0 + i * 16 + r + 8) * APITCH + kc + c];
                unsigned a2 = Au[(m0 + i * 16 + r)     * APITCH + kc + c + 4];
                unsigned a3 = Au[(m0 + i * 16 + r + 8) * APITCH + kc + c + 4];
#pragma unroll
                for (int j = 0; j < 4; j++) {
                    asm volatile(
                        "mma.sync.aligned.m16n8k8.row.col.f32.tf32.tf32.f32 "
                        "{%0,%1,%2,%3},{%4,%5,%6,%7},{%8,%9},{%0,%1,%2,%3};\n"
                        : "+f"(acc[i][j][0]), "+f"(acc[i][j][1]),
                          "+f"(acc[i][j][2]), "+f"(acc[i][j][3])
                        : "r"(a0), "r"(a1), "r"(a2), "r"(a3),
                          "r"(bf[j][0]), "r"(bf[j][1]));
                }
            }
        }
        __syncthreads();
    }

    // ---- store C tile ----
#pragma unroll
    for (int i = 0; i < 4; i++) {
        int row0 = by * 128 + m0 + i * 16 + r;
#pragma unroll
        for (int j = 0; j < 4; j++) {
            int col = bx * 128 + n0 + j * 8 + 2 * c;
            if (row0 < M)
                *(float2*)(C + (long long)row0 * DMF + col) =
                    make_float2(acc[i][j][0], acc[i][j][1]);
            if (row0 + 8 < M)
                *(float2*)(C + (long long)(row0 + 8) * DMF + col) =
                    make_float2(acc[i][j][2], acc[i][j][3]);
        }
    }

    // ---- fused attention-score epilogue (head == bx) ----
    float asr[4][2], adr[4][2];
#pragma unroll
    for (int j = 0; j < 4; j++) {
#pragma unroll
        for (int p = 0; p < 2; p++) {
            int colL = n0 + j * 8 + 2 * c + p;
            asr[j][p] = a_s[bx * HIDD + colL];
            adr[j][p] = a_d[bx * HIDD + colL];
        }
    }
#pragma unroll
    for (int i = 0; i < 4; i++) {
        float ps_lo = 0.f, ps_hi = 0.f, pd_lo = 0.f, pd_hi = 0.f;
#pragma unroll
        for (int j = 0; j < 4; j++) {
            ps_lo = fmaf(acc[i][j][0], asr[j][0], fmaf(acc[i][j][1], asr[j][1], ps_lo));
            ps_hi = fmaf(acc[i][j][2], asr[j][0], fmaf(acc[i][j][3], asr[j][1], ps_hi));
            pd_lo = fmaf(acc[i][j][0], adr[j][0], fmaf(acc[i][j][1], adr[j][1], pd_lo));
            pd_hi = fmaf(acc[i][j][2], adr[j][0], fmaf(acc[i][j][3], adr[j][1], pd_hi));
        }
#pragma unroll
        for (int off = 1; off < 4; off <<= 1) {
            ps_lo += __shfl_xor_sync(0xffffffffu, ps_lo, off);
            ps_hi += __shfl_xor_sync(0xffffffffu, ps_hi, off);
            pd_lo += __shfl_xor_sync(0xffffffffu, pd_lo, off);
            pd_hi += __shfl_xor_sync(0xffffffffu, pd_hi, off);
        }
        if (c == 0) {
            int row = by * 128 + m0 + i * 16 + r;
            if (row < M) {
                atomicAdd(&d_ssrc[row * NHEAD + bx], ps_lo);
                atomicAdd(&d_sdst[row * NHEAD + bx], pd_lo);
            }
            if (row + 8 < M) {
                atomicAdd(&d_ssrc[(row + 8) * NHEAD + bx], ps_hi);
                atomicAdd(&d_sdst[(row + 8) * NHEAD + bx], pd_hi);
            }
        }
    }
}

__global__ void zero_scores_kernel() {
    int i = blockIdx.x * blockDim.x + threadIdx.x;
    if (i < NN * NHEAD) { d_ssrc[i] = 0.f; d_sdst[i] = 0.f; }
}

// ---------------- CSR build (once per launch) ----------------
__global__ void zero_deg_kernel() {
    int n = blockIdx.x * blockDim.x + threadIdx.x;
    if (n < NN) d_deg[n] = 0;
}

__global__ void count_deg_kernel(const int* __restrict__ ei) {
    int e = blockIdx.x * blockDim.x + threadIdx.x;
    if (e >= ET) return;
    int dst = (e < EE) ? ei[EE + e] : e - EE;
    atomicAdd(&d_deg[dst], 1);
}

__global__ void __launch_bounds__(1024)
scan_kernel() {
    __shared__ int partial[1024];
    const int C = (NN + 1023) / 1024;       // 49
    int t = threadIdx.x;
    int lo = t * C, hi = min(lo + C, NN);
    int s = 0;
    for (int i = lo; i < hi; i++) s += d_deg[i];
    partial[t] = s;
    __syncthreads();
    for (int off = 1; off < 1024; off <<= 1) {
        int v = partial[t];
        int add = (t >= off) ? partial[t - off] : 0;
        __syncthreads();
        partial[t] = v + add;
        __syncthreads();
    }
    int run = (t == 0) ? 0 : partial[t - 1];
    for (int i = lo; i < hi; i++) {
        d_rowptr[i] = run;
        d_cursor[i] = run;
        run += d_deg[i];
    }
}

__global__ void scatter_kernel(const int* __restrict__ ei) {
    int e = blockIdx.x * blockDim.x + threadIdx.x;
    if (e >= ET) return;
    int dst = (e < EE) ? ei[EE + e] : e - EE;
    int pos = atomicAdd(&d_cursor[dst], 1);
    d_eid[pos] = e;
}

// ---------------- fused softmax + CSR gather aggregation ------------------
__global__ void __launch_bounds__(128)
aggregate_fused_kernel(const int* __restrict__ ei,
                       const float* __restrict__ bias) {
    __shared__ int    sm_src[128];
    __shared__ float  sm_w[NHEAD][128];
    __shared__ float4 sred[128];

    const int n = blockIdx.x;
    const int t = threadIdx.x;
    const int w = t >> 5;                 // warp == head

    const int start = d_rowptr[n];
    const int deg   = d_deg[n];

    float4 sd = *(const float4*)(d_sdst + n * NHEAD);

    // ---- phase 1: segment max over incoming edges ----
    float4 lm = make_float4(-1e30f, -1e30f, -1e30f, -1e30f);
    for (int b = t; b < deg; b += 128) {
        int e = d_eid[start + b];
        int s = (e < EE) ? ei[e] : e - EE;
        float4 ss = *(const float4*)(d_ssrc + s * NHEAD);
        lm.x = fmaxf(lm.x, leakyf(ss.x + sd.x));
        lm.y = fmaxf(lm.y, leakyf(ss.y + sd.y));
        lm.z = fmaxf(lm.z, leakyf(ss.z + sd.z));
        lm.w = fmaxf(lm.w, leakyf(ss.w + sd.w));
    }
    sred[t] = lm;
    __syncthreads();
#pragma unroll
    for (int off = 64; off; off >>= 1) {
        if (t < off) {
            float4 o = sred[t + off];
            float4 v = sred[t];
            v.x = fmaxf(v.x, o.x); v.y = fmaxf(v.y, o.y);
            v.z = fmaxf(v.z, o.z); v.w = fmaxf(v.w, o.w);
            sred[t] = v;
        }
        __syncthreads();
    }
    float4 m4 = sred[0];
    __syncthreads();

    // ---- phase 2: exp weights + denominator + weighted gather ----
    float4 lden = make_float4(0.f, 0.f, 0.f, 0.f);
    float4 acc  = make_float4(0.f, 0.f, 0.f, 0.f);

    for (int base = 0; base < deg; base += 128) {
        int cnt = min(128, deg - base);
        if (t < cnt) {
            int e = d_eid[start + base + t];
            int s = (e < EE) ? ei[e] : e - EE;
            sm_src[t] = s;
            float4 ss = *(const float4*)(d_ssrc + s * NHEAD);
            float4 ex;
            ex.x = expf(leakyf(ss.x + sd.x) - m4.x);
            ex.y = expf(leakyf(ss.y + sd.y) - m4.y);
            ex.z = expf(leakyf(ss.z + sd.z) - m4.z);
            ex.w = expf(leakyf(ss.w + sd.w) - m4.w);
            sm_w[0][t] = ex.x; sm_w[1][t] = ex.y;
            sm_w[2][t] = ex.z; sm_w[3][t] = ex.w;
            lden.x += ex.x; lden.y += ex.y; lden.z += ex.z; lden.w += ex.w;
        }
        __syncthreads();
#pragma unroll 2
        for (int i = 0; i < cnt; i++) {
            int s = sm_src[i];
            float wgt = sm_w[w][i];
            float4 hv = *(const float4*)(d_h + (long long)s * DMF + t * 4);
            acc.x = fmaf(wgt, hv.x, acc.x);
            acc.y = fmaf(wgt, hv.y, acc.y);
            acc.z = fmaf(wgt, hv.z, acc.z);
            acc.w = fmaf(wgt, hv.w, acc.w);
        }
        __syncthreads();
    }

    // ---- reduce denominator, normalize, add bias, store ----
    sred[t] = lden;
    __syncthreads();
#pragma unroll
    for (int off = 64; off; off >>= 1) {
        if (t < off) {
            float4 o = sred[t + off];
            float4 v = sred[t];
            v.x += o.x; v.y += o.y; v.z += o.z; v.w += o.w;
            sred[t] = v;
        }
        __syncthreads();
    }
    float4 den = sred[0];
    float rd = 1.0f / ((w == 0) ? den.x : (w == 1) ? den.y : (w == 2) ? den.z : den.w);

    float4 b = *(const float4*)(bias + t * 4);
    acc.x = fmaf(acc.x, rd, b.x);
    acc.y = fmaf(acc.y, rd, b.y);
    acc.z = fmaf(acc.z, rd, b.z);
    acc.w = fmaf(acc.w, rd, b.w);
    *(float4*)(d_agg + (long long)n * DMF + t * 4) = acc;
}

// ---------------- batch norm ----------------
__global__ void bn_zero_kernel() {
    int c = threadIdx.x;
    d_bnsum[c] = 0.f; d_bnss[c] = 0.f;
}

__global__ void __launch_bounds__(512)
bn_stats_kernel() {
    int c = threadIdx.x;
    int r0 = blockIdx.x * 64;
    int rend = min(r0 + 64, NN);
    float s = 0.f, ss = 0.f;
    for (int r = r0; r < rend; r++) {
        float v = d_agg[(long long)r * DMF + c];
        s += v; ss += v * v;
    }
    atomicAdd(&d_bnsum[c], s);
    atomicAdd(&d_bnss[c], ss);
}

__global__ void bn_finalize_kernel(const float* __restrict__ g,
                                   const float* __restrict__ be) {
    int c = threadIdx.x;
    float mean = d_bnsum[c] * (1.0f / NN);
    float var  = d_bnss[c] * (1.0f / NN) - mean * mean;
    float sc = g[c] * rsqrtf(var + BN_EPS);
    d_scale[c] = sc;
    d_shift[c] = be[c] - mean * sc;
}

__global__ void bn_apply_kernel() {
    int i = blockIdx.x * blockDim.x + threadIdx.x;
    if (i >= NN * DMF) return;
    int c = i & (DMF - 1);
    float v = d_agg[i] * d_scale[c] + d_shift[c];
    d_xb[i] = fmaxf(v, 0.f);
}

// last layer: BN + ReLU + mean/max pooling fused (no d_xb write)
__global__ void bn_apply_pool_kernel(const int* __restrict__ batch) {
    int i = blockIdx.x * blockDim.x + threadIdx.x;
    if (i >= NN * 128) return;              // float4 lanes
    int n = i >> 7, c4 = i & 127;
    int c = c4 * 4;
    float4 a = *(const float4*)(d_agg + (long long)n * DMF + c);
    float4 v;
    v.x = fmaxf(fmaf(a.x, d_scale[c + 0], d_shift[c + 0]), 0.f);
    v.y = fmaxf(fmaf(a.y, d_scale[c + 1], d_shift[c + 1]), 0.f);
    v.z = fmaxf(fmaf(a.z, d_scale[c + 2], d_shift[c + 2]), 0.f);
    v.w = fmaxf(fmaf(a.w, d_scale[c + 3], d_shift[c + 3]), 0.f);
    int g = batch[n];
    redAddV4(d_gsum + (long long)g * DMF + c, v);
    int* mp = d_gmaxi + (long long)g * DMF + c;
    atomicMax(mp + 0, __float_as_int(v.x));   // values >= 0 after ReLU
    atomicMax(mp + 1, __float_as_int(v.y));
    atomicMax(mp + 2, __float_as_int(v.z));
    atomicMax(mp + 3, __float_as_int(v.w));
}

// ---------------- pooling init ----------------
__global__ void pool_init_kernel() {
    int i = blockIdx.x * blockDim.x + threadIdx.x;
    if (i < GG * DMF) { d_gsum[i] = 0.f; d_gmaxi[i] = 0; }
    if (i < GG) d_gcnt[i] = 0.f;
}

__global__ void pool_cnt_kernel(const int* __restrict__ batch) {
    int n = blockIdx.x * blockDim.x + threadIdx.x;
    if (n < NN) atomicAdd(&d_gcnt[batch[n]], 1.0f);
}

// ---------------- graph-level MLP ----------------
__global__ void __launch_bounds__(128)
mlp1_kernel(const float* __restrict__ c1w, const float* __restrict__ c1b) {
    __shared__ float hrow[1024];
    int g = blockIdx.x, t = threadIdx.x;
    float cnt = fmaxf(d_gcnt[g], 1.0f);
    float inv = 1.0f / cnt;
    for (int c = t; c < DMF; c += 128) {
        hrow[c]       = d_gsum[g * DMF + c] * inv;
        hrow[DMF + c] = __int_as_float(d_gmaxi[g * DMF + c]);
    }
    __syncthreads();
    float acc = c1b[t];
    for (int k = 0; k < 1024; k++) acc = fmaf(hrow[k], c1w[k * 128 + t], acc);
    d_h1[g * 128 + t] = fmaxf(acc, 0.f);
}

__global__ void __launch_bounds__(64)
mlp2_kernel(const float* __restrict__ c2w, const float* __restrict__ c2b) {
    __shared__ float hrow[128];
    int g = blockIdx.x, t = threadIdx.x;
    for (int c = t; c < 128; c += 64) hrow[c] = d_h1[g * 128 + c];
    __syncthreads();
    float acc = c2b[t];
    for (int k = 0; k < 128; k++) acc = fmaf(hrow[k], c2w[k * 64 + t], acc);
    d_h2[g * 64 + t] = fmaxf(acc, 0.f);
}

__global__ void mlp3_kernel(const float* __restrict__ c3w,
                            const float* __restrict__ c3b,
                            float* __restrict__ out) {
    int g = blockIdx.x * blockDim.x + threadIdx.x;
    if (g >= GG) return;
    float acc = c3b[0];
    for (int k = 0; k < 64; k++) acc = fmaf(d_h2[g * 64 + k], c3w[k], acc);
    out[g] = 1.0f / (1.0f + expf(-acc));
}

// ---------------- launch ----------------
extern "C" void kernel_launch(void* const* d_in, const int* in_sizes, int n_in,
                              void* d_out, int out_size) {
    const float* x     = (const float*)d_in[0];
    const int*   ei    = (const int*)  d_in[1];
    const int*   batch = (const int*)  d_in[2];

    const float* W [3] = {(const float*)d_in[3],  (const float*)d_in[9],  (const float*)d_in[15]};
    const float* AS[3] = {(const float*)d_in[4],  (const float*)d_in[10], (const float*)d_in[16]};
    const float* AD[3] = {(const float*)d_in[5],  (const float*)d_in[11], (const float*)d_in[17]};
    const float* BB[3] = {(const float*)d_in[6],  (const float*)d_in[12], (const float*)d_in[18]};
    const float* GM[3] = {(const float*)d_in[7],  (const float*)d_in[13], (const float*)d_in[19]};
    const float* BE[3] = {(const float*)d_in[8],  (const float*)d_in[14], (const float*)d_in[20]};

    const float* c1w = (const float*)d_in[21];
    const float* c1b = (const float*)d_in[22];
    const float* c2w = (const float*)d_in[23];
    const float* c2b = (const float*)d_in[24];
    const float* c3w = (const float*)d_in[25];
    const float* c3b = (const float*)d_in[26];
    float* out = (float*)d_out;

    float* hbuf;  cudaGetSymbolAddress((void**)&hbuf,  d_h);
    float* xbuf;  cudaGetSymbolAddress((void**)&xbuf,  d_xb);

    const int KDIM[3] = {64, DMF, DMF};
    const int THR = 256;

    // ---- CSR build + pooling init (edge structure constant across layers) --
    zero_deg_kernel<<<(NN + THR - 1) / THR, THR>>>();
    count_deg_kernel<<<(ET + THR - 1) / THR, THR>>>(ei);
    scan_kernel<<<1, 1024>>>();
    scatter_kernel<<<(ET + THR - 1) / THR, THR>>>(ei);

    int pil = GG * DMF;
    pool_init_kernel<<<(pil + THR - 1) / THR, THR>>>();
    pool_cnt_kernel<<<(NN + THR - 1) / THR, THR>>>(batch);

    for (int l = 0; l < 3; l++) {
        const float* xin = (l == 0) ? x : xbuf;

        int sct = NN * NHEAD;
        zero_scores_kernel<<<(sct + THR - 1) / THR, THR>>>();

        dim3 ggrid(DMF / 128, (NN + 127) / 128);
        gemm_tf32_kernel<<<ggrid, 256>>>(xin, W[l], hbuf, NN, KDIM[l], AS[l], AD[l]);

        aggregate_fused_kernel<<<NN, 128>>>(ei, BB[l]);

        bn_zero_kernel<<<1, DMF>>>();
        bn_stats_kernel<<<(NN + 63) / 64, DMF>>>();
        bn_finalize_kernel<<<1, DMF>>>(GM[l], BE[l]);

        if (l < 2) {
            int nel = NN * DMF;
            bn_apply_kernel<<<(nel + THR - 1) / THR, THR>>>();
        } else {
            int pft = NN * 128;
            bn_apply_pool_kernel<<<(pft + THR - 1) / THR, THR>>>(batch);
        }
    }

    mlp1_kernel<<<GG, 128>>>(c1w, c1b);
    mlp2_kernel<<<GG, 64>>>(c2w, c2b);
    mlp3_kernel<<<(GG + 63) / 64, 64>>>(c3w, c3b, out);
}

// round 7
// speedup vs baseline: 2.2905x; 1.0234x over previous
#include <cuda_runtime.h>
#include <math.h>

#define NN    50000
#define EE    200000
#define ET    250000   // EE + NN self loops
#define GG    2000
#define DMF   512
#define NHEAD 4
#define HIDD  128
#define NEG_SLOPE 0.2f
#define BN_EPS 1e-5f

// ---------------- scratch (device globals; no allocation allowed) ----------
__device__ float d_h   [NN * DMF];     // h = x @ W  (per layer)
__device__ float d_xb  [NN * DMF];     // layer output / next layer input
__device__ float d_agg [NN * DMF];     // aggregated output (bias folded)
__device__ float d_ssrc[NN * NHEAD];
__device__ float d_sdst[NN * NHEAD];
__device__ float d_bnsum[DMF];
__device__ float d_bnss [DMF];
__device__ float d_scale[DMF];
__device__ float d_shift[DMF];
__device__ float d_gsum [GG * DMF];
__device__ int   d_gmaxi[GG * DMF];
__device__ float d_gcnt [GG];
__device__ float d_h1   [GG * 128];
__device__ float d_h2   [GG * 64];
// CSR (rebuilt each launch; edge structure constant across the 3 layers)
__device__ int   d_deg   [NN];
__device__ int   d_rowptr[NN];
__device__ int   d_cursor[NN];
__device__ int   d_eid   [ET];

// ---------------- helpers ----------------
__device__ __forceinline__ void redAddV4(float* p, float4 v) {
    asm volatile("red.global.add.v4.f32 [%0], {%1,%2,%3,%4};"
                 :: "l"(p), "f"(v.x), "f"(v.y), "f"(v.z), "f"(v.w) : "memory");
}

__device__ __forceinline__ void cpAsync16(void* smem_dst, const void* gsrc, int src_sz) {
    unsigned d = (unsigned)__cvta_generic_to_shared(smem_dst);
    asm volatile("cp.async.cg.shared.global [%0], [%1], 16, %2;"
                 :: "r"(d), "l"(gsrc), "r"(src_sz));
}

__device__ __forceinline__ float leakyf(float v) {
    return (v > 0.f) ? v : NEG_SLOPE * v;
}

// ---------------- TF32 GEMM + fused attention-score epilogue --------------
#define APITCH 20
#define BPITCH 136

__global__ void __launch_bounds__(256)
gemm_tf32_kernel(const float* __restrict__ A, const float* __restrict__ B,
                 float* __restrict__ C, int M, int K,
                 const float* __restrict__ a_s, const float* __restrict__ a_d) {
    __shared__ float As[2][128 * APITCH];
    __shared__ float Bs[2][16 * BPITCH];
    __shared__ float s_ps[4][128];
    __shared__ float s_pd[4][128];

    const int bx = blockIdx.x;   // N tile == head (0..3)
    const int by = blockIdx.y;   // M tile
    const int tid = threadIdx.x;
    const int warp = tid >> 5, lane = tid & 31;
    const int wr = warp & 1, wc = warp >> 1;      // 2 x 4 warp grid
    const int m0 = wr * 64, n0 = wc * 32;
    const int r = lane >> 2, c = lane & 3;

    float acc[4][4][4];
#pragma unroll
    for (int i = 0; i < 4; i++)
#pragma unroll
        for (int j = 0; j < 4; j++)
#pragma unroll
            for (int q = 0; q < 4; q++) acc[i][j][q] = 0.0f;

    const int KT = K >> 4;

    auto load_tile = [&](int st, int k0) {
#pragma unroll
        for (int p = 0; p < 2; p++) {
            int f = tid + p * 256;               // 0..511
            int m = f >> 2, ch = (f & 3) * 4;
            int gm = by * 128 + m;
            cpAsync16(&As[st][m * APITCH + ch],
                      A + (long long)gm * K + k0 + ch,
                      (gm < M) ? 16 : 0);
        }
#pragma unroll
        for (int p = 0; p < 2; p++) {
            int f = tid + p * 256;
            int kb = f >> 5, ch = (f & 31) * 4;
            cpAsync16(&Bs[st][kb * BPITCH + ch],
                      B + (long long)(k0 + kb) * DMF + bx * 128 + ch,
                      16);
        }
    };

    load_tile(0, 0);
    asm volatile("cp.async.commit_group;");

    for (int kt = 0; kt < KT; kt++) {
        const int st = kt & 1;
        if (kt + 1 < KT) load_tile(st ^ 1, (kt + 1) * 16);
        asm volatile("cp.async.commit_group;");
        asm volatile("cp.async.wait_group 1;");
        __syncthreads();

        const unsigned* Au = (const unsigned*)As[st];
        const unsigned* Bu = (const unsigned*)Bs[st];
#pragma unroll
        for (int ks = 0; ks < 2; ks++) {
            const int kc = ks * 8;
            unsigned bf[4][2];
#pragma unroll
            for (int j = 0; j < 4; j++) {
                bf[j][0] = Bu[(kc + c) * BPITCH + n0 + j * 8 + r];
                bf[j][1] = Bu[(kc + c + 4) * BPITCH + n0 + j * 8 + r];
            }
#pragma unroll
            for (int i = 0; i < 4; i++) {
                unsigned a0 = Au[(m0 + i * 16 + r)     * APITCH + kc + c];
                unsigned a1 = Au[(m0 + i * 16 + r + 8) * APITCH + kc + c];
                unsigned a2 = Au[(m0 + i * 16 + r)     * APITCH + kc + c + 4];
                unsigned a3 = Au[(m0 + i * 16 + r + 8) * APITCH + kc + c + 4];
#pragma unroll
                for (int j = 0; j < 4; j++) {
                    asm volatile(
                        "mma.sync.aligned.m16n8k8.row.col.f32.tf32.tf32.f32 "
                        "{%0,%1,%2,%3},{%4,%5,%6,%7},{%8,%9},{%0,%1,%2,%3};\n"
                        : "+f"(acc[i][j][0]), "+f"(acc[i][j][1]),
                          "+f"(acc[i][j][2]), "+f"(acc[i][j][3])
                        : "r"(a0), "r"(a1), "r"(a2), "r"(a3),
                          "r"(bf[j][0]), "r"(bf[j][1]));
                }
            }
        }
        __syncthreads();
    }

    // ---- store C tile ----
#pragma unroll
    for (int i = 0; i < 4; i++) {
        int row0 = by * 128 + m0 + i * 16 + r;
#pragma unroll
        for (int j = 0; j < 4; j++) {
            int col = bx * 128 + n0 + j * 8 + 2 * c;
            if (row0 < M)
                *(float2*)(C + (long long)row0 * DMF + col) =
                    make_float2(acc[i][j][0], acc[i][j][1]);
            if (row0 + 8 < M)
                *(float2*)(C + (long long)(row0 + 8) * DMF + col) =
                    make_float2(acc[i][j][2], acc[i][j][3]);
        }
    }

    // ---- fused attention-score epilogue (head == bx); smem reduce ----
    float asr[4][2], adr[4][2];
#pragma unroll
    for (int j = 0; j < 4; j++) {
#pragma unroll
        for (int p = 0; p < 2; p++) {
            int colL = n0 + j * 8 + 2 * c + p;
            asr[j][p] = a_s[bx * HIDD + colL];
            adr[j][p] = a_d[bx * HIDD + colL];
        }
    }
#pragma unroll
    for (int i = 0; i < 4; i++) {
        float ps_lo = 0.f, ps_hi = 0.f, pd_lo = 0.f, pd_hi = 0.f;
#pragma unroll
        for (int j = 0; j < 4; j++) {
            ps_lo = fmaf(acc[i][j][0], asr[j][0], fmaf(acc[i][j][1], asr[j][1], ps_lo));
            ps_hi = fmaf(acc[i][j][2], asr[j][0], fmaf(acc[i][j][3], asr[j][1], ps_hi));
            pd_lo = fmaf(acc[i][j][0], adr[j][0], fmaf(acc[i][j][1], adr[j][1], pd_lo));
            pd_hi = fmaf(acc[i][j][2], adr[j][0], fmaf(acc[i][j][3], adr[j][1], pd_hi));
        }
#pragma unroll
        for (int off = 1; off < 4; off <<= 1) {
            ps_lo += __shfl_xor_sync(0xffffffffu, ps_lo, off);
            ps_hi += __shfl_xor_sync(0xffffffffu, ps_hi, off);
            pd_lo += __shfl_xor_sync(0xffffffffu, pd_lo, off);
            pd_hi += __shfl_xor_sync(0xffffffffu, pd_hi, off);
        }
        if (c == 0) {
            int rl = m0 + i * 16 + r;
            s_ps[wc][rl]     = ps_lo;  s_pd[wc][rl]     = pd_lo;
            s_ps[wc][rl + 8] = ps_hi;  s_pd[wc][rl + 8] = pd_hi;
        }
    }
    __syncthreads();
    if (tid < 128) {
        int row = by * 128 + tid;
        if (row < M) {
            d_ssrc[row * NHEAD + bx] =
                s_ps[0][tid] + s_ps[1][tid] + s_ps[2][tid] + s_ps[3][tid];
            d_sdst[row * NHEAD + bx] =
                s_pd[0][tid] + s_pd[1][tid] + s_pd[2][tid] + s_pd[3][tid];
        }
    }
}

// ---------------- CSR build (once per launch) ----------------
__global__ void zero_deg_kernel() {
    int n = blockIdx.x * blockDim.x + threadIdx.x;
    if (n < NN) d_deg[n] = 0;
}

__global__ void count_deg_kernel(const int* __restrict__ ei) {
    int e = blockIdx.x * blockDim.x + threadIdx.x;
    if (e >= ET) return;
    int dst = (e < EE) ? ei[EE + e] : e - EE;
    atomicAdd(&d_deg[dst], 1);
}

__global__ void __launch_bounds__(1024)
scan_kernel() {
    __shared__ int partial[1024];
    const int C = (NN + 1023) / 1024;       // 49
    int t = threadIdx.x;
    int lo = t * C, hi = min(lo + C, NN);
    int s = 0;
    for (int i = lo; i < hi; i++) s += d_deg[i];
    partial[t] = s;
    __syncthreads();
    for (int off = 1; off < 1024; off <<= 1) {
        int v = partial[t];
        int add = (t >= off) ? partial[t - off] : 0;
        __syncthreads();
        partial[t] = v + add;
        __syncthreads();
    }
    int run = (t == 0) ? 0 : partial[t - 1];
    for (int i = lo; i < hi; i++) {
        d_rowptr[i] = run;
        d_cursor[i] = run;
        run += d_deg[i];
    }
}

__global__ void scatter_kernel(const int* __restrict__ ei) {
    int e = blockIdx.x * blockDim.x + threadIdx.x;
    if (e >= ET) return;
    int dst = (e < EE) ? ei[EE + e] : e - EE;
    int pos = atomicAdd(&d_cursor[dst], 1);
    d_eid[pos] = e;
}

// ---------------- warp-per-node fused softmax + gather aggregation --------
__global__ void __launch_bounds__(256)
aggregate_warp_kernel(const int* __restrict__ ei,
                      const float* __restrict__ bias) {
    const int lane = threadIdx.x & 31;
    const int n = blockIdx.x * 8 + (threadIdx.x >> 5);
    if (n >= NN) return;

    const int start = d_rowptr[n];
    const int deg   = d_deg[n];
    const int head  = lane >> 3;          // lane's 16 cols = [lane*16, +16)

    float4 sd = *(const float4*)(d_sdst + n * NHEAD);

    // ---- phase 1: per-head segment max (warp-parallel over edges) ----
    float4 m4 = make_float4(-1e30f, -1e30f, -1e30f, -1e30f);
    for (int b = lane; b < deg; b += 32) {
        int e = d_eid[start + b];
        int s = (e < EE) ? ei[e] : e - EE;
        float4 ss = *(const float4*)(d_ssrc + s * NHEAD);
        m4.x = fmaxf(m4.x, leakyf(ss.x + sd.x));
        m4.y = fmaxf(m4.y, leakyf(ss.y + sd.y));
        m4.z = fmaxf(m4.z, leakyf(ss.z + sd.z));
        m4.w = fmaxf(m4.w, leakyf(ss.w + sd.w));
    }
#pragma unroll
    for (int off = 16; off; off >>= 1) {
        m4.x = fmaxf(m4.x, __shfl_xor_sync(0xffffffffu, m4.x, off));
        m4.y = fmaxf(m4.y, __shfl_xor_sync(0xffffffffu, m4.y, off));
        m4.z = fmaxf(m4.z, __shfl_xor_sync(0xffffffffu, m4.z, off));
        m4.w = fmaxf(m4.w, __shfl_xor_sync(0xffffffffu, m4.w, off));
    }

    // ---- phase 2: exp weights + denominator + weighted gather ----
    float4 acc0 = make_float4(0.f, 0.f, 0.f, 0.f);
    float4 acc1 = acc0, acc2 = acc0, acc3 = acc0;
    float4 lden = acc0;

    for (int base = 0; base < deg; base += 32) {
        int cnt = min(32, deg - base);
        int s = 0;
        float4 w4 = make_float4(0.f, 0.f, 0.f, 0.f);
        if (lane < cnt) {
            int e = d_eid[start + base + lane];
            s = (e < EE) ? ei[e] : e - EE;
            float4 ss = *(const float4*)(d_ssrc + s * NHEAD);
            w4.x = expf(leakyf(ss.x + sd.x) - m4.x);
            w4.y = expf(leakyf(ss.y + sd.y) - m4.y);
            w4.z = expf(leakyf(ss.z + sd.z) - m4.z);
            w4.w = expf(leakyf(ss.w + sd.w) - m4.w);
            lden.x += w4.x; lden.y += w4.y; lden.z += w4.z; lden.w += w4.w;
        }
        for (int i = 0; i < cnt; i++) {
            int   si = __shfl_sync(0xffffffffu, s, i);
            float wx = __shfl_sync(0xffffffffu, w4.x, i);
            float wy = __shfl_sync(0xffffffffu, w4.y, i);
            float wz = __shfl_sync(0xffffffffu, w4.z, i);
            float ww = __shfl_sync(0xffffffffu, w4.w, i);
            float wgt = (head == 0) ? wx : (head == 1) ? wy : (head == 2) ? wz : ww;
            const float4* hp = (const float4*)(d_h + (long long)si * DMF) + lane * 4;
            float4 h0 = hp[0], h1 = hp[1], h2 = hp[2], h3 = hp[3];
            acc0.x = fmaf(wgt, h0.x, acc0.x); acc0.y = fmaf(wgt, h0.y, acc0.y);
            acc0.z = fmaf(wgt, h0.z, acc0.z); acc0.w = fmaf(wgt, h0.w, acc0.w);
            acc1.x = fmaf(wgt, h1.x, acc1.x); acc1.y = fmaf(wgt, h1.y, acc1.y);
            acc1.z = fmaf(wgt, h1.z, acc1.z); acc1.w = fmaf(wgt, h1.w, acc1.w);
            acc2.x = fmaf(wgt, h2.x, acc2.x); acc2.y = fmaf(wgt, h2.y, acc2.y);
            acc2.z = fmaf(wgt, h2.z, acc2.z); acc2.w = fmaf(wgt, h2.w, acc2.w);
            acc3.x = fmaf(wgt, h3.x, acc3.x); acc3.y = fmaf(wgt, h3.y, acc3.y);
            acc3.z = fmaf(wgt, h3.z, acc3.z); acc3.w = fmaf(wgt, h3.w, acc3.w);
        }
    }

#pragma unroll
    for (int off = 16; off; off >>= 1) {
        lden.x += __shfl_xor_sync(0xffffffffu, lden.x, off);
        lden.y += __shfl_xor_sync(0xffffffffu, lden.y, off);
        lden.z += __shfl_xor_sync(0xffffffffu, lden.z, off);
        lden.w += __shfl_xor_sync(0xffffffffu, lden.w, off);
    }
    float den = (head == 0) ? lden.x : (head == 1) ? lden.y
              : (head == 2) ? lden.z : lden.w;
    float rd = 1.0f / den;

    const float4* bp = (const float4*)bias + lane * 4;
    float4* op = (float4*)(d_agg + (long long)n * DMF) + lane * 4;
    float4 b0 = bp[0], b1 = bp[1], b2 = bp[2], b3 = bp[3];
    float4 o;
    o.x = fmaf(acc0.x, rd, b0.x); o.y = fmaf(acc0.y, rd, b0.y);
    o.z = fmaf(acc0.z, rd, b0.z); o.w = fmaf(acc0.w, rd, b0.w); op[0] = o;
    o.x = fmaf(acc1.x, rd, b1.x); o.y = fmaf(acc1.y, rd, b1.y);
    o.z = fmaf(acc1.z, rd, b1.z); o.w = fmaf(acc1.w, rd, b1.w); op[1] = o;
    o.x = fmaf(acc2.x, rd, b2.x); o.y = fmaf(acc2.y, rd, b2.y);
    o.z = fmaf(acc2.z, rd, b2.z); o.w = fmaf(acc2.w, rd, b2.w); op[2] = o;
    o.x = fmaf(acc3.x, rd, b3.x); o.y = fmaf(acc3.y, rd, b3.y);
    o.z = fmaf(acc3.z, rd, b3.z); o.w = fmaf(acc3.w, rd, b3.w); op[3] = o;
}

// ---------------- batch norm ----------------
__global__ void bn_zero_kernel() {
    int c = threadIdx.x;
    d_bnsum[c] = 0.f; d_bnss[c] = 0.f;
}

__global__ void __launch_bounds__(512)
bn_stats_kernel() {
    int c = threadIdx.x;
    int r0 = blockIdx.x * 64;
    int rend = min(r0 + 64, NN);
    float s = 0.f, ss = 0.f;
    for (int r = r0; r < rend; r++) {
        float v = d_agg[(long long)r * DMF + c];
        s += v; ss += v * v;
    }
    atomicAdd(&d_bnsum[c], s);
    atomicAdd(&d_bnss[c], ss);
}

__global__ void bn_finalize_kernel(const float* __restrict__ g,
                                   const float* __restrict__ be) {
    int c = threadIdx.x;
    float mean = d_bnsum[c] * (1.0f / NN);
    float var  = d_bnss[c] * (1.0f / NN) - mean * mean;
    float sc = g[c] * rsqrtf(var + BN_EPS);
    d_scale[c] = sc;
    d_shift[c] = be[c] - mean * sc;
}

__global__ void bn_apply_kernel() {
    int i = blockIdx.x * blockDim.x + threadIdx.x;
    if (i >= NN * DMF) return;
    int c = i & (DMF - 1);
    float v = d_agg[i] * d_scale[c] + d_shift[c];
    d_xb[i] = fmaxf(v, 0.f);
}

// last layer: BN + ReLU + mean/max pooling fused (no d_xb write)
__global__ void bn_apply_pool_kernel(const int* __restrict__ batch) {
    int i = blockIdx.x * blockDim.x + threadIdx.x;
    if (i >= NN * 128) return;              // float4 lanes
    int n = i >> 7, c4 = i & 127;
    int c = c4 * 4;
    float4 a = *(const float4*)(d_agg + (long long)n * DMF + c);
    float4 v;
    v.x = fmaxf(fmaf(a.x, d_scale[c + 0], d_shift[c + 0]), 0.f);
    v.y = fmaxf(fmaf(a.y, d_scale[c + 1], d_shift[c + 1]), 0.f);
    v.z = fmaxf(fmaf(a.z, d_scale[c + 2], d_shift[c + 2]), 0.f);
    v.w = fmaxf(fmaf(a.w, d_scale[c + 3], d_shift[c + 3]), 0.f);
    int g = batch[n];
    redAddV4(d_gsum + (long long)g * DMF + c, v);
    int* mp = d_gmaxi + (long long)g * DMF + c;
    atomicMax(mp + 0, __float_as_int(v.x));   // values >= 0 after ReLU
    atomicMax(mp + 1, __float_as_int(v.y));
    atomicMax(mp + 2, __float_as_int(v.z));
    atomicMax(mp + 3, __float_as_int(v.w));
}

// ---------------- pooling init ----------------
__global__ void pool_init_kernel() {
    int i = blockIdx.x * blockDim.x + threadIdx.x;
    if (i < GG * DMF) { d_gsum[i] = 0.f; d_gmaxi[i] = 0; }
    if (i < GG) d_gcnt[i] = 0.f;
}

__global__ void pool_cnt_kernel(const int* __restrict__ batch) {
    int n = blockIdx.x * blockDim.x + threadIdx.x;
    if (n < NN) atomicAdd(&d_gcnt[batch[n]], 1.0f);
}

// ---------------- graph-level MLP ----------------
// 8 graphs per block: c1w element reused 8x from a register.
__global__ void __launch_bounds__(128)
mlp1_kernel(const float* __restrict__ c1w, const float* __restrict__ c1b) {
    __shared__ float hrow[8][1024];
    int g0 = blockIdx.x * 8, t = threadIdx.x;
#pragma unroll
    for (int gi = 0; gi < 8; gi++) {
        int g = g0 + gi;
        float inv = 1.0f / fmaxf(d_gcnt[g], 1.0f);
        for (int c = t; c < DMF; c += 128) {
            hrow[gi][c]       = d_gsum[g * DMF + c] * inv;
            hrow[gi][DMF + c] = __int_as_float(d_gmaxi[g * DMF + c]);
        }
    }
    __syncthreads();
    float acc[8];
    float b = c1b[t];
#pragma unroll
    for (int gi = 0; gi < 8; gi++) acc[gi] = b;
    for (int k = 0; k < 1024; k++) {
        float wv = c1w[k * 128 + t];
#pragma unroll
        for (int gi = 0; gi < 8; gi++)
            acc[gi] = fmaf(hrow[gi][k], wv, acc[gi]);
    }
#pragma unroll
    for (int gi = 0; gi < 8; gi++)
        d_h1[(g0 + gi) * 128 + t] = fmaxf(acc[gi], 0.f);
}

__global__ void __launch_bounds__(64)
mlp2_kernel(const float* __restrict__ c2w, const float* __restrict__ c2b) {
    __shared__ float hrow[128];
    int g = blockIdx.x, t = threadIdx.x;
    for (int c = t; c < 128; c += 64) hrow[c] = d_h1[g * 128 + c];
    __syncthreads();
    float acc = c2b[t];
    for (int k = 0; k < 128; k++) acc = fmaf(hrow[k], c2w[k * 64 + t], acc);
    d_h2[g * 64 + t] = fmaxf(acc, 0.f);
}

__global__ void mlp3_kernel(const float* __restrict__ c3w,
                            const float* __restrict__ c3b,
                            float* __restrict__ out) {
    int g = blockIdx.x * blockDim.x + threadIdx.x;
    if (g >= GG) return;
    float acc = c3b[0];
    for (int k = 0; k < 64; k++) acc = fmaf(d_h2[g * 64 + k], c3w[k], acc);
    out[g] = 1.0f / (1.0f + expf(-acc));
}

// ---------------- launch ----------------
extern "C" void kernel_launch(void* const* d_in, const int* in_sizes, int n_in,
                              void* d_out, int out_size) {
    const float* x     = (const float*)d_in[0];
    const int*   ei    = (const int*)  d_in[1];
    const int*   batch = (const int*)  d_in[2];

    const float* W [3] = {(const float*)d_in[3],  (const float*)d_in[9],  (const float*)d_in[15]};
    const float* AS[3] = {(const float*)d_in[4],  (const float*)d_in[10], (const float*)d_in[16]};
    const float* AD[3] = {(const float*)d_in[5],  (const float*)d_in[11], (const float*)d_in[17]};
    const float* BB[3] = {(const float*)d_in[6],  (const float*)d_in[12], (const float*)d_in[18]};
    const float* GM[3] = {(const float*)d_in[7],  (const float*)d_in[13], (const float*)d_in[19]};
    const float* BE[3] = {(const float*)d_in[8],  (const float*)d_in[14], (const float*)d_in[20]};

    const float* c1w = (const float*)d_in[21];
    const float* c1b = (const float*)d_in[22];
    const float* c2w = (const float*)d_in[23];
    const float* c2b = (const float*)d_in[24];
    const float* c3w = (const float*)d_in[25];
    const float* c3b = (const float*)d_in[26];
    float* out = (float*)d_out;

    float* hbuf;  cudaGetSymbolAddress((void**)&hbuf,  d_h);
    float* xbuf;  cudaGetSymbolAddress((void**)&xbuf,  d_xb);

    const int KDIM[3] = {64, DMF, DMF};
    const int THR = 256;

    // ---- CSR build + pooling init (edge structure constant across layers) --
    zero_deg_kernel<<<(NN + THR - 1) / THR, THR>>>();
    count_deg_kernel<<<(ET + THR - 1) / THR, THR>>>(ei);
    scan_kernel<<<1, 1024>>>();
    scatter_kernel<<<(ET + THR - 1) / THR, THR>>>(ei);

    int pil = GG * DMF;
    pool_init_kernel<<<(pil + THR - 1) / THR, THR>>>();
    pool_cnt_kernel<<<(NN + THR - 1) / THR, THR>>>(batch);

    for (int l = 0; l < 3; l++) {
        const float* xin = (l == 0) ? x : xbuf;

        dim3 ggrid(DMF / 128, (NN + 127) / 128);
        gemm_tf32_kernel<<<ggrid, 256>>>(xin, W[l], hbuf, NN, KDIM[l], AS[l], AD[l]);

        aggregate_warp_kernel<<<(NN + 7) / 8, 256>>>(ei, BB[l]);

        bn_zero_kernel<<<1, DMF>>>();
        bn_stats_kernel<<<(NN + 63) / 64, DMF>>>();
        bn_finalize_kernel<<<1, DMF>>>(GM[l], BE[l]);

        if (l < 2) {
            int nel = NN * DMF;
            bn_apply_kernel<<<(nel + THR - 1) / THR, THR>>>();
        } else {
            int pft = NN * 128;
            bn_apply_pool_kernel<<<(pft + THR - 1) / THR, THR>>>(batch);
        }
    }

    mlp1_kernel<<<GG / 8, 128>>>(c1w, c1b);
    mlp2_kernel<<<GG, 64>>>(c2w, c2b);
    mlp3_kernel<<<(GG + 63) / 64, 64>>>(c3w, c3b, out);
}